// round 2
// baseline (speedup 1.0000x reference)
#include <cuda_runtime.h>
#include <cstdint>
#include <cstddef>

#define NB 8
#define LL 2048
#define KK 30
#define CH 128
#define NEDGE (NB*LL*KK)   // 491520

static constexpr size_t V_SIZE = (size_t)NB * LL * CH;           // 2,097,152
static constexpr size_t E_SIZE = (size_t)NB * LL * KK * CH;      // 62,914,560
static constexpr size_t E_OFF  = V_SIZE;
static constexpr size_t I_OFF  = V_SIZE + E_SIZE;

// -------- scratch (device globals; no allocations allowed) --------
__device__ float g_dnb[NB*LL*KK];      // sorted neighbor distances (reference-bit-exact D)
__device__ int   g_eidx[NB*LL*KK];     // sorted neighbor indices
__device__ float g_O[NB*LL*9];         // per-residue orientation frame (rows b, n1, x)
__device__ float g_feat[39*NEDGE];     // edge features, f-major: g_feat[f*NEDGE + e]

// ---------------- small helpers ----------------
__device__ __forceinline__ float dot3(const float* a, const float* b) {
    return a[0]*b[0] + a[1]*b[1] + a[2]*b[2];
}
__device__ __forceinline__ void cross3(const float* a, const float* b, float* o) {
    o[0] = a[1]*b[2] - a[2]*b[1];
    o[1] = a[2]*b[0] - a[0]*b[2];
    o[2] = a[0]*b[1] - a[1]*b[0];
}
__device__ __forceinline__ void norm3(float* v) {
    float n = sqrtf(v[0]*v[0] + v[1]*v[1] + v[2]*v[2]);
    n = fmaxf(n, 1e-12f);
    v[0] /= n; v[1] /= n; v[2] /= n;
}
__device__ __forceinline__ float sgnf(float v) {
    return (v > 0.f) ? 1.f : ((v < 0.f) ? -1.f : 0.f);
}

__device__ __forceinline__ unsigned long long warp_max64(unsigned long long v) {
    const unsigned FULL = 0xffffffffu;
    #pragma unroll
    for (int o = 16; o > 0; o >>= 1) {
        unsigned long long ov = __shfl_xor_sync(FULL, v, o);
        if (ov > v) v = ov;
    }
    return v;
}

// ======================================================================
// Kernel 1: exact KNN matching jax.lax.top_k(-D) bit-for-bit.
// Key = (float_bits(D) << 32) | j  where D = sqrt(((dx*dx+dy*dy)+dz*dz)+1e-6)
// computed with non-contracted rn arithmetic (XLA emits mul/add w/o FMA).
// One warp per query; warp-distributed top-32 set with replace-max inserts.
// ======================================================================
__global__ void __launch_bounds__(512)
knn_kernel(const float* __restrict__ X, float* __restrict__ out)
{
    __shared__ float4 pts[LL];                 // 32 KB: all CA of this batch
    const int b = blockIdx.y;
    const float* Xb = X + (size_t)b * LL * 12;

    for (int t = threadIdx.x; t < LL; t += blockDim.x) {
        float x = Xb[t*12 + 3], y = Xb[t*12 + 4], z = Xb[t*12 + 5];
        pts[t] = make_float4(x, y, z, 0.f);
    }
    __syncthreads();

    const int wid  = threadIdx.x >> 5;
    const int lane = threadIdx.x & 31;
    const int i = blockIdx.x * 16 + wid;       // query index
    const float4 q = pts[i];
    const unsigned FULL = 0xffffffffu;

    auto keyof = [&](const float4& p, int j) -> unsigned long long {
        float dx = __fsub_rn(p.x, q.x);
        float dy = __fsub_rn(p.y, q.y);
        float dz = __fsub_rn(p.z, q.z);
        float d2 = __fadd_rn(__fadd_rn(__fmul_rn(dx,dx), __fmul_rn(dy,dy)),
                             __fmul_rn(dz,dz));
        float D  = sqrtf(__fadd_rn(d2, 1e-6f));   // sqrt.rn — matches XLA
        return ((unsigned long long)__float_as_uint(D) << 32) | (unsigned)j;
    };

    // round 0: fill all 32 slots with candidates j = 0..31
    unsigned long long cur = keyof(pts[lane], lane);
    unsigned long long thr = warp_max64(cur);

    for (int t = 1; t < LL/32; t++) {
        const int j = t*32 + lane;
        unsigned long long kk = keyof(pts[j], j);
        unsigned bal = __ballot_sync(FULL, kk < thr);
        while (bal) {
            int s = __ffs(bal) - 1;
            bal &= bal - 1;
            unsigned long long bk = __shfl_sync(FULL, kk, s);
            if (bk < thr) {                     // warp-uniform branch
                unsigned m = __ballot_sync(FULL, cur == thr);  // unique key
                int repl = __ffs(m) - 1;
                if (lane == repl) cur = bk;
                thr = warp_max64(cur);
            }
        }
    }

    // bitonic sort 32 keys across the warp, ascending
    #pragma unroll
    for (int k = 2; k <= 32; k <<= 1) {
        #pragma unroll
        for (int j = k >> 1; j >= 1; j >>= 1) {
            unsigned long long ok = __shfl_xor_sync(FULL, cur, j);
            bool up    = ((lane & k) == 0);
            bool lower = ((lane & j) == 0);
            bool mineLess = (cur < ok);
            bool takeOther = up ? (lower ? !mineLess : mineLess)
                                : (lower ? mineLess : !mineLess);
            if (takeOther) cur = ok;
        }
    }

    if (lane < KK) {
        int e = (b*LL + i)*KK + lane;
        int nidx = (int)(cur & 0xffffffffu);
        g_dnb[e]  = __uint_as_float((unsigned)(cur >> 32));
        g_eidx[e] = nidx;
        out[I_OFF + (size_t)e] = (float)nidx;
    }
}

// ======================================================================
// Kernel 2: node features (dihedrals -> 6) @ W_node + LN; also builds O.
// One 128-thread block per residue.
// ======================================================================
__global__ void __launch_bounds__(128)
node_kernel(const float* __restrict__ X,
            const float* __restrict__ Wn, const float* __restrict__ bn,
            const float* __restrict__ gn, const float* __restrict__ betan,
            float* __restrict__ out)
{
    const int idx = blockIdx.x;          // b*LL + i
    const int b = idx / LL, i = idx % LL;
    const float* Xb = X + (size_t)b * LL * 12;

    __shared__ float feat[6];
    __shared__ float red[4];
    __shared__ float stats[2];

    const int tid = threadIdx.x;
    const int wid = tid >> 5, lane = tid & 31;

    if (tid < 3) {
        int t = 3*i + tid - 1;
        float ang = 0.f;
        if (t >= 0 && t <= 3*LL - 4) {
            float P[4][3];
            #pragma unroll
            for (int a = 0; a < 4; a++) {
                int g = t + a;
                const float* ptr = Xb + (g/3)*12 + (g%3)*3;
                P[a][0] = ptr[0]; P[a][1] = ptr[1]; P[a][2] = ptr[2];
            }
            float u2[3], u1[3], u0[3], n2[3], n1[3];
            #pragma unroll
            for (int c = 0; c < 3; c++) {
                u2[c] = P[1][c] - P[0][c];
                u1[c] = P[2][c] - P[1][c];
                u0[c] = P[3][c] - P[2][c];
            }
            norm3(u2); norm3(u1); norm3(u0);
            cross3(u2, u1, n2); norm3(n2);
            cross3(u1, u0, n1); norm3(n1);
            float cd = dot3(n2, n1);
            cd = fminf(fmaxf(cd, -1.f + 1e-7f), 1.f - 1e-7f);
            ang = sgnf(dot3(u2, n1)) * acosf(cd);
        }
        feat[tid]     = cosf(ang);
        feat[tid + 3] = sinf(ang);
    }
    if (tid == 3) {
        const float* pr = Xb + i*12;
        float N[3]  = {pr[0], pr[1], pr[2]};
        float CA[3] = {pr[3], pr[4], pr[5]};
        float C[3]  = {pr[6], pr[7], pr[8]};
        float nca[3], cac[3];
        #pragma unroll
        for (int c = 0; c < 3; c++) { nca[c] = CA[c] - N[c]; cac[c] = C[c] - CA[c]; }
        norm3(nca); norm3(cac);
        float n1[3]; cross3(nca, cac, n1); norm3(n1);
        float bb[3];
        #pragma unroll
        for (int c = 0; c < 3; c++) bb[c] = cac[c] - nca[c];
        norm3(bb);
        float xx[3]; cross3(bb, n1, xx); norm3(xx);
        float* o = g_O + (size_t)idx * 9;
        o[0]=bb[0]; o[1]=bb[1]; o[2]=bb[2];
        o[3]=n1[0]; o[4]=n1[1]; o[5]=n1[2];
        o[6]=xx[0]; o[7]=xx[1]; o[8]=xx[2];
    }
    __syncthreads();

    float acc = bn[tid];
    #pragma unroll
    for (int f = 0; f < 6; f++) acc += feat[f] * Wn[f*CH + tid];

    // layernorm over the 128 channels (two-pass, matching jnp.var)
    float s = acc;
    #pragma unroll
    for (int o = 16; o > 0; o >>= 1) s += __shfl_down_sync(0xffffffffu, s, o);
    if (lane == 0) red[wid] = s;
    __syncthreads();
    if (tid == 0) stats[0] = (red[0] + red[1] + red[2] + red[3]) * (1.f/128.f);
    __syncthreads();
    float d = acc - stats[0];
    float s2 = d * d;
    #pragma unroll
    for (int o = 16; o > 0; o >>= 1) s2 += __shfl_down_sync(0xffffffffu, s2, o);
    if (lane == 0) red[wid] = s2;
    __syncthreads();
    if (tid == 0) {
        float var = (red[0] + red[1] + red[2] + red[3]) * (1.f/128.f);
        stats[1] = sqrtf(var + 1e-5f);
    }
    __syncthreads();
    out[(size_t)idx * CH + tid] = d / stats[1] * gn[tid] + betan[tid];
}

// ======================================================================
// Kernel 3: edge features (39 per edge), one thread per edge, f-major out
// ======================================================================
__global__ void __launch_bounds__(256)
efeat_kernel(const float* __restrict__ X)
{
    const int e = blockIdx.x * 256 + threadIdx.x;
    if (e >= NEDGE) return;
    const int bi = e / KK;                 // b*LL + i
    const int b = bi / LL, i = bi % LL;
    const int j = g_eidx[e];
    const float D = g_dnb[e];

    float F[39];

    // positional encodings (16) — cos then sin, same libdevice fns as XLA
    const float d = (float)(j - i);
    const float cfac = -0.5756462732485115f;   // -(log(10000)/16)
    #pragma unroll
    for (int m = 0; m < 8; m++) {
        float freq = expf((float)(2*m) * cfac);
        float a = d * freq;
        F[m]     = cosf(a);
        F[8 + m] = sinf(a);
    }

    // RBF (16)
    #pragma unroll
    for (int m = 0; m < 16; m++) {
        float mu = (float)m * (20.0f / 15.0f);
        float t = (D - mu) / 1.25f;
        F[16 + m] = expf(-(t * t));
    }

    // orientations (7)
    const float* Oi = g_O + (size_t)bi * 9;
    const float* Oj = g_O + ((size_t)b*LL + j) * 9;
    float oi[9], oj[9];
    #pragma unroll
    for (int t = 0; t < 9; t++) { oi[t] = Oi[t]; oj[t] = Oj[t]; }
    const float* Xi = X + (size_t)bi * 12 + 3;
    const float* Xj = X + ((size_t)b*LL + j) * 12 + 3;
    float dX[3] = {Xj[0]-Xi[0], Xj[1]-Xi[1], Xj[2]-Xi[2]};
    float du[3] = { oi[0]*dX[0] + oi[1]*dX[1] + oi[2]*dX[2],
                    oi[3]*dX[0] + oi[4]*dX[1] + oi[5]*dX[2],
                    oi[6]*dX[0] + oi[7]*dX[1] + oi[8]*dX[2] };
    norm3(du);
    F[32] = du[0]; F[33] = du[1]; F[34] = du[2];

    // R = Oi^T * Oj
    float R[3][3];
    #pragma unroll
    for (int r = 0; r < 3; r++)
        #pragma unroll
        for (int c = 0; c < 3; c++)
            R[r][c] = oi[r]*oj[c] + oi[3+r]*oj[3+c] + oi[6+r]*oj[6+c];

    float Rxx = R[0][0], Ryy = R[1][1], Rzz = R[2][2];
    float m0 = 0.5f * sqrtf(fabsf((1.f + ( Rxx - Ryy - Rzz)) + 1e-10f));
    float m1 = 0.5f * sqrtf(fabsf((1.f + (-Rxx + Ryy - Rzz)) + 1e-10f));
    float m2 = 0.5f * sqrtf(fabsf((1.f + (-Rxx - Ryy + Rzz)) + 1e-10f));
    float qx = sgnf(R[2][1] - R[1][2]) * m0;
    float qy = sgnf(R[0][2] - R[2][0]) * m1;
    float qz = sgnf(R[1][0] - R[0][1]) * m2;
    float qw = sqrtf(fmaxf(1.f + Rxx + Ryy + Rzz, 0.f)) * 0.5f;
    float qn = sqrtf(qx*qx + qy*qy + qz*qz + qw*qw);
    qn = fmaxf(qn, 1e-12f);
    F[35] = qx/qn; F[36] = qy/qn; F[37] = qz/qn; F[38] = qw/qn;

    #pragma unroll
    for (int f = 0; f < 39; f++) g_feat[(size_t)f * NEDGE + e] = F[f];
}

// ======================================================================
// Kernel 4: edge GEMM ([491520 x 39] @ [39 x 128]) + bias + layernorm
// Block = 128 threads (one channel each), TILE = 32 edges.
// W in registers; features broadcast from shared via LDS.128.
// ======================================================================
#define TILE 32
__global__ void __launch_bounds__(128)
egemm_kernel(const float* __restrict__ We, const float* __restrict__ be,
             const float* __restrict__ ge, const float* __restrict__ betae,
             float* __restrict__ out)
{
    const int e0 = blockIdx.x * TILE;
    const int c = threadIdx.x;
    __shared__ __align__(16) float ft[39][TILE];   // features, f-major
    __shared__ float outs[TILE][CH];
    __shared__ float mu_s[TILE], rs_s[TILE];

    float w[39];
    #pragma unroll
    for (int f = 0; f < 39; f++) w[f] = We[f*CH + c];
    const float bias = be[c], gg = ge[c], bb = betae[c];

    for (int idx = c; idx < 39*TILE; idx += CH) {
        int f = idx / TILE, e = idx % TILE;
        ft[f][e] = g_feat[(size_t)f * NEDGE + e0 + e];
    }
    __syncthreads();

    float acc[TILE];
    #pragma unroll
    for (int e = 0; e < TILE; e++) acc[e] = bias;
    #pragma unroll
    for (int f = 0; f < 39; f++) {
        float wf = w[f];
        #pragma unroll
        for (int e4 = 0; e4 < TILE/4; e4++) {
            float4 v = *reinterpret_cast<const float4*>(&ft[f][e4*4]);
            acc[e4*4 + 0] += v.x * wf;
            acc[e4*4 + 1] += v.y * wf;
            acc[e4*4 + 2] += v.z * wf;
            acc[e4*4 + 3] += v.w * wf;
        }
    }

    #pragma unroll
    for (int e = 0; e < TILE; e++) outs[e][c] = acc[e];
    __syncthreads();

    const int wid = c >> 5, lane = c & 31;
    #pragma unroll
    for (int q = 0; q < 8; q++) {
        int e = wid * 8 + q;
        float v0 = outs[e][lane], v1 = outs[e][lane+32];
        float v2 = outs[e][lane+64], v3 = outs[e][lane+96];
        float s = v0 + v1 + v2 + v3;
        #pragma unroll
        for (int o = 16; o > 0; o >>= 1) s += __shfl_xor_sync(0xffffffffu, s, o);
        float mu = s * (1.f/128.f);
        float d0 = v0-mu, d1 = v1-mu, d2 = v2-mu, d3 = v3-mu;
        float s2 = d0*d0 + d1*d1 + d2*d2 + d3*d3;
        #pragma unroll
        for (int o = 16; o > 0; o >>= 1) s2 += __shfl_xor_sync(0xffffffffu, s2, o);
        if (lane == 0) {
            mu_s[e] = mu;
            rs_s[e] = sqrtf(s2 * (1.f/128.f) + 1e-5f);
        }
    }
    __syncthreads();

    const size_t base = E_OFF + (size_t)e0 * CH;
    #pragma unroll
    for (int e = 0; e < TILE; e++) {
        out[base + (size_t)e * CH + c] = (acc[e] - mu_s[e]) / rs_s[e] * gg + bb;
    }
}

// ======================================================================
extern "C" void kernel_launch(void* const* d_in, const int* in_sizes, int n_in,
                              void* d_out, int out_size)
{
    const float* X      = (const float*)d_in[0];
    // d_in[1] = mask (all ones for this problem; unused)
    const float* W_node = (const float*)d_in[2];
    const float* b_node = (const float*)d_in[3];
    const float* g_node = (const float*)d_in[4];
    const float* be_node= (const float*)d_in[5];
    const float* W_edge = (const float*)d_in[6];
    const float* b_edge = (const float*)d_in[7];
    const float* g_edge = (const float*)d_in[8];
    const float* be_edge= (const float*)d_in[9];
    float* out = (float*)d_out;

    knn_kernel<<<dim3(LL/16, NB), 512>>>(X, out);
    node_kernel<<<NB*LL, 128>>>(X, W_node, b_node, g_node, be_node, out);
    efeat_kernel<<<(NEDGE + 255)/256, 256>>>(X);
    egemm_kernel<<<NEDGE/TILE, 128>>>(W_edge, b_edge, g_edge, be_edge, out);
}

// round 3
// speedup vs baseline: 1.0256x; 1.0256x over previous
#include <cuda_runtime.h>
#include <cstdint>
#include <cstddef>

#define NB 8
#define LL 2048
#define KK 30
#define CH 128
#define NEDGE (NB*LL*KK)   // 491520

static constexpr size_t V_SIZE = (size_t)NB * LL * CH;           // 2,097,152
static constexpr size_t E_SIZE = (size_t)NB * LL * KK * CH;      // 62,914,560
static constexpr size_t E_OFF  = V_SIZE;
static constexpr size_t I_OFF  = V_SIZE + E_SIZE;

// -------- scratch (device globals; no allocations allowed) --------
__device__ float g_dnb[NB*LL*KK];      // sorted neighbor distances (reference-bit-exact D)
__device__ int   g_eidx[NB*LL*KK];     // sorted neighbor indices
__device__ float g_O[NB*LL*9];         // per-residue orientation frame (rows b, n1, x)
__device__ float g_feat[39*NEDGE];     // edge features, f-major: g_feat[f*NEDGE + e]

// ---------------- small helpers ----------------
__device__ __forceinline__ float dot3(const float* a, const float* b) {
    return a[0]*b[0] + a[1]*b[1] + a[2]*b[2];
}
__device__ __forceinline__ void cross3(const float* a, const float* b, float* o) {
    o[0] = a[1]*b[2] - a[2]*b[1];
    o[1] = a[2]*b[0] - a[0]*b[2];
    o[2] = a[0]*b[1] - a[1]*b[0];
}
__device__ __forceinline__ void norm3(float* v) {
    float n = sqrtf(v[0]*v[0] + v[1]*v[1] + v[2]*v[2]);
    n = fmaxf(n, 1e-12f);
    v[0] /= n; v[1] /= n; v[2] /= n;
}
__device__ __forceinline__ float sgnf(float v) {
    return (v > 0.f) ? 1.f : ((v < 0.f) ? -1.f : 0.f);
}

// packed fp32x2 ops (sm_100+/sm_103a)
__device__ __forceinline__ unsigned long long pack2(float x, float y) {
    unsigned long long r;
    asm("mov.b64 %0, {%1, %2};" : "=l"(r) : "f"(x), "f"(y));
    return r;
}
__device__ __forceinline__ float2 unpack2(unsigned long long v) {
    float2 r;
    asm("mov.b64 {%0, %1}, %2;" : "=f"(r.x), "=f"(r.y) : "l"(v));
    return r;
}
__device__ __forceinline__ void fma2(unsigned long long& d,
                                     unsigned long long a, unsigned long long b) {
    asm("fma.rn.f32x2 %0, %1, %2, %0;" : "+l"(d) : "l"(a), "l"(b));
}

// ======================================================================
// Kernel 1: exact KNN matching jax.lax.top_k(-D) bit-for-bit.
// Key = (float_bits(D) << 32) | j, D = sqrt(((dx*dx+dy*dy)+dz*dz)+1e-6)
// with non-contracted rn arithmetic. Cheap fma-d2 prefilter gates the
// exact-key computation; threshold via 2x REDUX.MAX.
// ======================================================================
__global__ void __launch_bounds__(512)
knn_kernel(const float* __restrict__ X, float* __restrict__ out)
{
    __shared__ float4 pts[LL];                 // 32 KB: all CA of this batch
    const int b = blockIdx.y;
    const float* Xb = X + (size_t)b * LL * 12;

    for (int t = threadIdx.x; t < LL; t += blockDim.x) {
        pts[t] = make_float4(Xb[t*12 + 3], Xb[t*12 + 4], Xb[t*12 + 5], 0.f);
    }
    __syncthreads();

    const int wid  = threadIdx.x >> 5;
    const int lane = threadIdx.x & 31;
    const int i = blockIdx.x * 16 + wid;       // query index
    const float4 q = pts[i];
    const unsigned FULL = 0xffffffffu;

    auto exact_key = [&](float px, float py, float pz, int j) -> unsigned long long {
        float dx = __fsub_rn(px, q.x);
        float dy = __fsub_rn(py, q.y);
        float dz = __fsub_rn(pz, q.z);
        float d2 = __fadd_rn(__fadd_rn(__fmul_rn(dx,dx), __fmul_rn(dy,dy)),
                             __fmul_rn(dz,dz));
        float D  = sqrtf(__fadd_rn(d2, 1e-6f));   // sqrt.rn — matches XLA
        return ((unsigned long long)__float_as_uint(D) << 32) | (unsigned)j;
    };

    // round 0: fill all 32 slots with candidates j = 0..31
    float4 p = pts[lane];
    unsigned long long cur = exact_key(p.x, p.y, p.z, lane);

    unsigned long long thr;
    float thr_d2;
    auto update_thr = [&]() {
        unsigned hi = __reduce_max_sync(FULL, (unsigned)(cur >> 32));
        unsigned lo = __reduce_max_sync(FULL,
                          ((unsigned)(cur >> 32) == hi) ? (unsigned)cur : 0u);
        thr = ((unsigned long long)hi << 32) | lo;
        float D = __uint_as_float(hi);
        thr_d2 = D * D * 1.00002f;     // conservative: covers fma/rn/sqrt ulps
    };
    update_thr();

    for (int t = 1; t < LL/32; t++) {
        const int j = t*32 + lane;
        p = pts[j];
        float dx = p.x - q.x, dy = p.y - q.y, dz = p.z - q.z;
        float d2c = fmaf(dx, dx, fmaf(dy, dy, dz*dz));
        bool pass = d2c <= thr_d2;
        unsigned bal = __ballot_sync(FULL, pass);
        if (!bal) continue;                       // warp-uniform
        unsigned long long kk = pass ? exact_key(p.x, p.y, p.z, j) : ~0ull;
        do {
            int s = __ffs(bal) - 1;
            bal &= bal - 1;
            unsigned long long bk = __shfl_sync(FULL, kk, s);
            if (bk < thr) {                       // warp-uniform
                unsigned m = __ballot_sync(FULL, cur == thr);  // keys unique
                if (lane == (__ffs(m) - 1)) cur = bk;
                update_thr();
            }
        } while (bal);
    }

    // bitonic sort 32 keys across the warp, ascending
    #pragma unroll
    for (int k = 2; k <= 32; k <<= 1) {
        #pragma unroll
        for (int j = k >> 1; j >= 1; j >>= 1) {
            unsigned long long ok = __shfl_xor_sync(FULL, cur, j);
            bool up    = ((lane & k) == 0);
            bool lower = ((lane & j) == 0);
            bool mineLess = (cur < ok);
            bool takeOther = up ? (lower ? !mineLess : mineLess)
                                : (lower ? mineLess : !mineLess);
            if (takeOther) cur = ok;
        }
    }

    if (lane < KK) {
        int e = (b*LL + i)*KK + lane;
        int nidx = (int)(cur & 0xffffffffu);
        g_dnb[e]  = __uint_as_float((unsigned)(cur >> 32));
        g_eidx[e] = nidx;
        out[I_OFF + (size_t)e] = (float)nidx;
    }
}

// ======================================================================
// Kernel 2: node features (dihedrals -> 6) @ W_node + LN; also builds O.
// ======================================================================
__global__ void __launch_bounds__(128)
node_kernel(const float* __restrict__ X,
            const float* __restrict__ Wn, const float* __restrict__ bn,
            const float* __restrict__ gn, const float* __restrict__ betan,
            float* __restrict__ out)
{
    const int idx = blockIdx.x;          // b*LL + i
    const int b = idx / LL, i = idx % LL;
    const float* Xb = X + (size_t)b * LL * 12;

    __shared__ float feat[6];
    __shared__ float red[4];
    __shared__ float stats[2];

    const int tid = threadIdx.x;
    const int wid = tid >> 5, lane = tid & 31;

    if (tid < 3) {
        int t = 3*i + tid - 1;
        float ang = 0.f;
        if (t >= 0 && t <= 3*LL - 4) {
            float P[4][3];
            #pragma unroll
            for (int a = 0; a < 4; a++) {
                int g = t + a;
                const float* ptr = Xb + (g/3)*12 + (g%3)*3;
                P[a][0] = ptr[0]; P[a][1] = ptr[1]; P[a][2] = ptr[2];
            }
            float u2[3], u1[3], u0[3], n2[3], n1[3];
            #pragma unroll
            for (int c = 0; c < 3; c++) {
                u2[c] = P[1][c] - P[0][c];
                u1[c] = P[2][c] - P[1][c];
                u0[c] = P[3][c] - P[2][c];
            }
            norm3(u2); norm3(u1); norm3(u0);
            cross3(u2, u1, n2); norm3(n2);
            cross3(u1, u0, n1); norm3(n1);
            float cd = dot3(n2, n1);
            cd = fminf(fmaxf(cd, -1.f + 1e-7f), 1.f - 1e-7f);
            ang = sgnf(dot3(u2, n1)) * acosf(cd);
        }
        feat[tid]     = cosf(ang);
        feat[tid + 3] = sinf(ang);
    }
    if (tid == 3) {
        const float* pr = Xb + i*12;
        float N[3]  = {pr[0], pr[1], pr[2]};
        float CA[3] = {pr[3], pr[4], pr[5]};
        float C[3]  = {pr[6], pr[7], pr[8]};
        float nca[3], cac[3];
        #pragma unroll
        for (int c = 0; c < 3; c++) { nca[c] = CA[c] - N[c]; cac[c] = C[c] - CA[c]; }
        norm3(nca); norm3(cac);
        float n1[3]; cross3(nca, cac, n1); norm3(n1);
        float bb[3];
        #pragma unroll
        for (int c = 0; c < 3; c++) bb[c] = cac[c] - nca[c];
        norm3(bb);
        float xx[3]; cross3(bb, n1, xx); norm3(xx);
        float* o = g_O + (size_t)idx * 9;
        o[0]=bb[0]; o[1]=bb[1]; o[2]=bb[2];
        o[3]=n1[0]; o[4]=n1[1]; o[5]=n1[2];
        o[6]=xx[0]; o[7]=xx[1]; o[8]=xx[2];
    }
    __syncthreads();

    float acc = bn[tid];
    #pragma unroll
    for (int f = 0; f < 6; f++) acc += feat[f] * Wn[f*CH + tid];

    float s = acc;
    #pragma unroll
    for (int o = 16; o > 0; o >>= 1) s += __shfl_down_sync(0xffffffffu, s, o);
    if (lane == 0) red[wid] = s;
    __syncthreads();
    if (tid == 0) stats[0] = (red[0] + red[1] + red[2] + red[3]) * (1.f/128.f);
    __syncthreads();
    float d = acc - stats[0];
    float s2 = d * d;
    #pragma unroll
    for (int o = 16; o > 0; o >>= 1) s2 += __shfl_down_sync(0xffffffffu, s2, o);
    if (lane == 0) red[wid] = s2;
    __syncthreads();
    if (tid == 0) {
        float var = (red[0] + red[1] + red[2] + red[3]) * (1.f/128.f);
        stats[1] = sqrtf(var + 1e-5f);
    }
    __syncthreads();
    out[(size_t)idx * CH + tid] = d / stats[1] * gn[tid] + betan[tid];
}

// ======================================================================
// Kernel 3: edge features (39 per edge), one thread per edge, f-major out
// ======================================================================
__global__ void __launch_bounds__(256)
efeat_kernel(const float* __restrict__ X)
{
    const int e = blockIdx.x * 256 + threadIdx.x;
    if (e >= NEDGE) return;
    const int bi = e / KK;                 // b*LL + i
    const int b = bi / LL, i = bi % LL;
    const int j = g_eidx[e];
    const float D = g_dnb[e];

    float F[39];

    const float d = (float)(j - i);
    const float cfac = -0.5756462732485115f;   // -(log(10000)/16)
    #pragma unroll
    for (int m = 0; m < 8; m++) {
        float freq = expf((float)(2*m) * cfac);
        float a = d * freq;
        F[m]     = cosf(a);
        F[8 + m] = sinf(a);
    }

    #pragma unroll
    for (int m = 0; m < 16; m++) {
        float mu = (float)m * (20.0f / 15.0f);
        float t = (D - mu) / 1.25f;
        F[16 + m] = expf(-(t * t));
    }

    const float* Oi = g_O + (size_t)bi * 9;
    const float* Oj = g_O + ((size_t)b*LL + j) * 9;
    float oi[9], oj[9];
    #pragma unroll
    for (int t = 0; t < 9; t++) { oi[t] = Oi[t]; oj[t] = Oj[t]; }
    const float* Xi = X + (size_t)bi * 12 + 3;
    const float* Xj = X + ((size_t)b*LL + j) * 12 + 3;
    float dX[3] = {Xj[0]-Xi[0], Xj[1]-Xi[1], Xj[2]-Xi[2]};
    float du[3] = { oi[0]*dX[0] + oi[1]*dX[1] + oi[2]*dX[2],
                    oi[3]*dX[0] + oi[4]*dX[1] + oi[5]*dX[2],
                    oi[6]*dX[0] + oi[7]*dX[1] + oi[8]*dX[2] };
    norm3(du);
    F[32] = du[0]; F[33] = du[1]; F[34] = du[2];

    float R[3][3];
    #pragma unroll
    for (int r = 0; r < 3; r++)
        #pragma unroll
        for (int c = 0; c < 3; c++)
            R[r][c] = oi[r]*oj[c] + oi[3+r]*oj[3+c] + oi[6+r]*oj[6+c];

    float Rxx = R[0][0], Ryy = R[1][1], Rzz = R[2][2];
    float m0 = 0.5f * sqrtf(fabsf((1.f + ( Rxx - Ryy - Rzz)) + 1e-10f));
    float m1 = 0.5f * sqrtf(fabsf((1.f + (-Rxx + Ryy - Rzz)) + 1e-10f));
    float m2 = 0.5f * sqrtf(fabsf((1.f + (-Rxx - Ryy + Rzz)) + 1e-10f));
    float qx = sgnf(R[2][1] - R[1][2]) * m0;
    float qy = sgnf(R[0][2] - R[2][0]) * m1;
    float qz = sgnf(R[1][0] - R[0][1]) * m2;
    float qw = sqrtf(fmaxf(1.f + Rxx + Ryy + Rzz, 0.f)) * 0.5f;
    float qn = sqrtf(qx*qx + qy*qy + qz*qz + qw*qw);
    qn = fmaxf(qn, 1e-12f);
    F[35] = qx/qn; F[36] = qy/qn; F[37] = qz/qn; F[38] = qw/qn;

    #pragma unroll
    for (int f = 0; f < 39; f++) g_feat[(size_t)f * NEDGE + e] = F[f];
}

// ======================================================================
// Kernel 4: edge GEMM ([491520 x 39] @ [39 x 128]) + bias + layernorm.
// 64 threads/block; thread t owns channels t and t+64; TILE=32 edges.
// Mainloop uses packed fma.rn.f32x2 (2 fp32 FMA / instr).
// ======================================================================
#define TILE 32
__global__ void __launch_bounds__(64)
egemm_kernel(const float* __restrict__ We, const float* __restrict__ be,
             const float* __restrict__ ge, const float* __restrict__ betae,
             float* __restrict__ out)
{
    const int e0 = blockIdx.x * TILE;
    const int t = threadIdx.x;            // 0..63
    const int c0 = t, c1 = t + 64;
    __shared__ __align__(16) float ft[39][TILE];   // 5 KB, rows 128B-aligned
    __shared__ float outs[TILE][CH];               // 16 KB
    __shared__ float mu_s[TILE], irs_s[TILE];

    float w0[39], w1[39];
    #pragma unroll
    for (int f = 0; f < 39; f++) {
        w0[f] = We[f*CH + c0];
        w1[f] = We[f*CH + c1];
    }
    const float bias0 = be[c0], bias1 = be[c1];
    const float gg0 = ge[c0], gg1 = ge[c1];
    const float bb0 = betae[c0], bb1 = betae[c1];

    for (int idx = t; idx < 39*TILE; idx += 64) {
        int f = idx >> 5, e = idx & 31;
        ft[f][e] = g_feat[(size_t)f * NEDGE + e0 + e];
    }
    __syncthreads();

    unsigned long long acc0[16], acc1[16];
    const unsigned long long bi0 = pack2(bias0, bias0);
    const unsigned long long bi1 = pack2(bias1, bias1);
    #pragma unroll
    for (int m = 0; m < 16; m++) { acc0[m] = bi0; acc1[m] = bi1; }

    #pragma unroll
    for (int f = 0; f < 39; f++) {
        const unsigned long long wa = pack2(w0[f], w0[f]);
        const unsigned long long wb = pack2(w1[f], w1[f]);
        const ulonglong2* row = reinterpret_cast<const ulonglong2*>(&ft[f][0]);
        #pragma unroll
        for (int k = 0; k < 8; k++) {
            ulonglong2 v = row[k];            // LDS.128 broadcast: edges 4k..4k+3
            fma2(acc0[2*k  ], wa, v.x);
            fma2(acc0[2*k+1], wa, v.y);
            fma2(acc1[2*k  ], wb, v.x);
            fma2(acc1[2*k+1], wb, v.y);
        }
    }

    #pragma unroll
    for (int m = 0; m < 16; m++) {
        float2 p0 = unpack2(acc0[m]);
        float2 p1 = unpack2(acc1[m]);
        outs[2*m  ][c0] = p0.x;
        outs[2*m+1][c0] = p0.y;
        outs[2*m  ][c1] = p1.x;
        outs[2*m+1][c1] = p1.y;
    }
    __syncthreads();

    const int wwid = t >> 5, lane = t & 31;   // 2 warps, 16 edges each
    #pragma unroll
    for (int q = 0; q < 16; q++) {
        int e = wwid * 16 + q;
        float v0 = outs[e][lane], v1 = outs[e][lane+32];
        float v2 = outs[e][lane+64], v3 = outs[e][lane+96];
        float s = v0 + v1 + v2 + v3;
        #pragma unroll
        for (int o = 16; o > 0; o >>= 1) s += __shfl_xor_sync(0xffffffffu, s, o);
        float mu = s * (1.f/128.f);
        float d0 = v0-mu, d1 = v1-mu, d2 = v2-mu, d3 = v3-mu;
        float s2 = d0*d0 + d1*d1 + d2*d2 + d3*d3;
        #pragma unroll
        for (int o = 16; o > 0; o >>= 1) s2 += __shfl_xor_sync(0xffffffffu, s2, o);
        if (lane == 0) {
            mu_s[e] = mu;
            irs_s[e] = 1.f / sqrtf(s2 * (1.f/128.f) + 1e-5f);
        }
    }
    __syncthreads();

    const size_t base = E_OFF + (size_t)e0 * CH;
    #pragma unroll
    for (int m = 0; m < 16; m++) {
        float2 p0 = unpack2(acc0[m]);
        float2 p1 = unpack2(acc1[m]);
        int ea = 2*m, ebb = 2*m+1;
        float mua = mu_s[ea], ia = irs_s[ea];
        float mub = mu_s[ebb], ib = irs_s[ebb];
        out[base + (size_t)ea  * CH + c0] = (p0.x - mua) * ia * gg0 + bb0;
        out[base + (size_t)ebb * CH + c0] = (p0.y - mub) * ib * gg0 + bb0;
        out[base + (size_t)ea  * CH + c1] = (p1.x - mua) * ia * gg1 + bb1;
        out[base + (size_t)ebb * CH + c1] = (p1.y - mub) * ib * gg1 + bb1;
    }
}

// ======================================================================
extern "C" void kernel_launch(void* const* d_in, const int* in_sizes, int n_in,
                              void* d_out, int out_size)
{
    const float* X      = (const float*)d_in[0];
    // d_in[1] = mask (all ones; unused)
    const float* W_node = (const float*)d_in[2];
    const float* b_node = (const float*)d_in[3];
    const float* g_node = (const float*)d_in[4];
    const float* be_node= (const float*)d_in[5];
    const float* W_edge = (const float*)d_in[6];
    const float* b_edge = (const float*)d_in[7];
    const float* g_edge = (const float*)d_in[8];
    const float* be_edge= (const float*)d_in[9];
    float* out = (float*)d_out;

    knn_kernel<<<dim3(LL/16, NB), 512>>>(X, out);
    node_kernel<<<NB*LL, 128>>>(X, W_node, b_node, g_node, be_node, out);
    efeat_kernel<<<(NEDGE + 255)/256, 256>>>(X);
    egemm_kernel<<<NEDGE/TILE, 64>>>(W_edge, b_edge, g_edge, be_edge, out);
}

// round 4
// speedup vs baseline: 1.2683x; 1.2366x over previous
#include <cuda_runtime.h>
#include <cstdint>
#include <cstddef>

#define NB 8
#define LL 2048
#define KK 30
#define CH 128
#define NEDGE (NB*LL*KK)   // 491520

static constexpr size_t V_SIZE = (size_t)NB * LL * CH;           // 2,097,152
static constexpr size_t E_SIZE = (size_t)NB * LL * KK * CH;      // 62,914,560
static constexpr size_t E_OFF  = V_SIZE;
static constexpr size_t I_OFF  = V_SIZE + E_SIZE;

// -------- scratch (device globals; no allocations allowed) --------
__device__ float g_dnb[NB*LL*KK];      // sorted neighbor distances (reference-bit-exact D)
__device__ int   g_eidx[NB*LL*KK];     // sorted neighbor indices
__device__ float g_O[NB*LL*9];         // per-residue orientation frame (rows b, n1, x)
__device__ float g_feat[39*NEDGE];     // edge features, f-major: g_feat[f*NEDGE + e]

// ---------------- small helpers ----------------
__device__ __forceinline__ float dot3(const float* a, const float* b) {
    return a[0]*b[0] + a[1]*b[1] + a[2]*b[2];
}
__device__ __forceinline__ void cross3(const float* a, const float* b, float* o) {
    o[0] = a[1]*b[2] - a[2]*b[1];
    o[1] = a[2]*b[0] - a[0]*b[2];
    o[2] = a[0]*b[1] - a[1]*b[0];
}
__device__ __forceinline__ void norm3(float* v) {
    float n = sqrtf(v[0]*v[0] + v[1]*v[1] + v[2]*v[2]);
    n = fmaxf(n, 1e-12f);
    v[0] /= n; v[1] /= n; v[2] /= n;
}
__device__ __forceinline__ float sgnf(float v) {
    return (v > 0.f) ? 1.f : ((v < 0.f) ? -1.f : 0.f);
}

// packed fp32x2 ops (sm_100+/sm_103a)
__device__ __forceinline__ unsigned long long pack2(float x, float y) {
    unsigned long long r;
    asm("mov.b64 %0, {%1, %2};" : "=l"(r) : "f"(x), "f"(y));
    return r;
}
__device__ __forceinline__ float2 unpack2(unsigned long long v) {
    float2 r;
    asm("mov.b64 {%0, %1}, %2;" : "=f"(r.x), "=f"(r.y) : "l"(v));
    return r;
}
__device__ __forceinline__ void fma2(unsigned long long& d,
                                     unsigned long long a, unsigned long long b) {
    asm("fma.rn.f32x2 %0, %1, %2, %0;" : "+l"(d) : "l"(a), "l"(b));
}

// ======================================================================
// Kernel 1: exact KNN matching jax.lax.top_k(-D) bit-for-bit.
// ======================================================================
__global__ void __launch_bounds__(512)
knn_kernel(const float* __restrict__ X, float* __restrict__ out)
{
    __shared__ float4 pts[LL];                 // 32 KB: all CA of this batch
    const int b = blockIdx.y;
    const float* Xb = X + (size_t)b * LL * 12;

    for (int t = threadIdx.x; t < LL; t += blockDim.x) {
        pts[t] = make_float4(Xb[t*12 + 3], Xb[t*12 + 4], Xb[t*12 + 5], 0.f);
    }
    __syncthreads();

    const int wid  = threadIdx.x >> 5;
    const int lane = threadIdx.x & 31;
    const int i = blockIdx.x * 16 + wid;       // query index
    const float4 q = pts[i];
    const unsigned FULL = 0xffffffffu;

    auto exact_key = [&](float px, float py, float pz, int j) -> unsigned long long {
        float dx = __fsub_rn(px, q.x);
        float dy = __fsub_rn(py, q.y);
        float dz = __fsub_rn(pz, q.z);
        float d2 = __fadd_rn(__fadd_rn(__fmul_rn(dx,dx), __fmul_rn(dy,dy)),
                             __fmul_rn(dz,dz));
        float D  = sqrtf(__fadd_rn(d2, 1e-6f));   // sqrt.rn — matches XLA
        return ((unsigned long long)__float_as_uint(D) << 32) | (unsigned)j;
    };

    float4 p = pts[lane];
    unsigned long long cur = exact_key(p.x, p.y, p.z, lane);

    unsigned long long thr;
    float thr_d2;
    auto update_thr = [&]() {
        unsigned hi = __reduce_max_sync(FULL, (unsigned)(cur >> 32));
        unsigned lo = __reduce_max_sync(FULL,
                          ((unsigned)(cur >> 32) == hi) ? (unsigned)cur : 0u);
        thr = ((unsigned long long)hi << 32) | lo;
        float D = __uint_as_float(hi);
        thr_d2 = D * D * 1.00002f;     // conservative: covers fma/rn/sqrt ulps
    };
    update_thr();

    for (int t = 1; t < LL/32; t++) {
        const int j = t*32 + lane;
        p = pts[j];
        float dx = p.x - q.x, dy = p.y - q.y, dz = p.z - q.z;
        float d2c = fmaf(dx, dx, fmaf(dy, dy, dz*dz));
        bool pass = d2c <= thr_d2;
        unsigned bal = __ballot_sync(FULL, pass);
        if (!bal) continue;                       // warp-uniform
        unsigned long long kk = pass ? exact_key(p.x, p.y, p.z, j) : ~0ull;
        do {
            int s = __ffs(bal) - 1;
            bal &= bal - 1;
            unsigned long long bk = __shfl_sync(FULL, kk, s);
            if (bk < thr) {                       // warp-uniform
                unsigned m = __ballot_sync(FULL, cur == thr);  // keys unique
                if (lane == (__ffs(m) - 1)) cur = bk;
                update_thr();
            }
        } while (bal);
    }

    // bitonic sort 32 keys across the warp, ascending
    #pragma unroll
    for (int k = 2; k <= 32; k <<= 1) {
        #pragma unroll
        for (int j = k >> 1; j >= 1; j >>= 1) {
            unsigned long long ok = __shfl_xor_sync(FULL, cur, j);
            bool up    = ((lane & k) == 0);
            bool lower = ((lane & j) == 0);
            bool mineLess = (cur < ok);
            bool takeOther = up ? (lower ? !mineLess : mineLess)
                                : (lower ? mineLess : !mineLess);
            if (takeOther) cur = ok;
        }
    }

    if (lane < KK) {
        int e = (b*LL + i)*KK + lane;
        int nidx = (int)(cur & 0xffffffffu);
        g_dnb[e]  = __uint_as_float((unsigned)(cur >> 32));
        g_eidx[e] = nidx;
        out[I_OFF + (size_t)e] = (float)nidx;
    }
}

// ======================================================================
// Kernel 2: node features (dihedrals -> 6) @ W_node + LN; also builds O.
// ======================================================================
__global__ void __launch_bounds__(128)
node_kernel(const float* __restrict__ X,
            const float* __restrict__ Wn, const float* __restrict__ bn,
            const float* __restrict__ gn, const float* __restrict__ betan,
            float* __restrict__ out)
{
    const int idx = blockIdx.x;          // b*LL + i
    const int b = idx / LL, i = idx % LL;
    const float* Xb = X + (size_t)b * LL * 12;

    __shared__ float feat[6];
    __shared__ float red[4];
    __shared__ float stats[2];

    const int tid = threadIdx.x;
    const int wid = tid >> 5, lane = tid & 31;

    if (tid < 3) {
        int t = 3*i + tid - 1;
        float ang = 0.f;
        if (t >= 0 && t <= 3*LL - 4) {
            float P[4][3];
            #pragma unroll
            for (int a = 0; a < 4; a++) {
                int g = t + a;
                const float* ptr = Xb + (g/3)*12 + (g%3)*3;
                P[a][0] = ptr[0]; P[a][1] = ptr[1]; P[a][2] = ptr[2];
            }
            float u2[3], u1[3], u0[3], n2[3], n1[3];
            #pragma unroll
            for (int c = 0; c < 3; c++) {
                u2[c] = P[1][c] - P[0][c];
                u1[c] = P[2][c] - P[1][c];
                u0[c] = P[3][c] - P[2][c];
            }
            norm3(u2); norm3(u1); norm3(u0);
            cross3(u2, u1, n2); norm3(n2);
            cross3(u1, u0, n1); norm3(n1);
            float cd = dot3(n2, n1);
            cd = fminf(fmaxf(cd, -1.f + 1e-7f), 1.f - 1e-7f);
            ang = sgnf(dot3(u2, n1)) * acosf(cd);
        }
        feat[tid]     = cosf(ang);
        feat[tid + 3] = sinf(ang);
    }
    if (tid == 3) {
        const float* pr = Xb + i*12;
        float N[3]  = {pr[0], pr[1], pr[2]};
        float CA[3] = {pr[3], pr[4], pr[5]};
        float C[3]  = {pr[6], pr[7], pr[8]};
        float nca[3], cac[3];
        #pragma unroll
        for (int c = 0; c < 3; c++) { nca[c] = CA[c] - N[c]; cac[c] = C[c] - CA[c]; }
        norm3(nca); norm3(cac);
        float n1[3]; cross3(nca, cac, n1); norm3(n1);
        float bb[3];
        #pragma unroll
        for (int c = 0; c < 3; c++) bb[c] = cac[c] - nca[c];
        norm3(bb);
        float xx[3]; cross3(bb, n1, xx); norm3(xx);
        float* o = g_O + (size_t)idx * 9;
        o[0]=bb[0]; o[1]=bb[1]; o[2]=bb[2];
        o[3]=n1[0]; o[4]=n1[1]; o[5]=n1[2];
        o[6]=xx[0]; o[7]=xx[1]; o[8]=xx[2];
    }
    __syncthreads();

    float acc = bn[tid];
    #pragma unroll
    for (int f = 0; f < 6; f++) acc += feat[f] * Wn[f*CH + tid];

    float s = acc;
    #pragma unroll
    for (int o = 16; o > 0; o >>= 1) s += __shfl_down_sync(0xffffffffu, s, o);
    if (lane == 0) red[wid] = s;
    __syncthreads();
    if (tid == 0) stats[0] = (red[0] + red[1] + red[2] + red[3]) * (1.f/128.f);
    __syncthreads();
    float d = acc - stats[0];
    float s2 = d * d;
    #pragma unroll
    for (int o = 16; o > 0; o >>= 1) s2 += __shfl_down_sync(0xffffffffu, s2, o);
    if (lane == 0) red[wid] = s2;
    __syncthreads();
    if (tid == 0) {
        float var = (red[0] + red[1] + red[2] + red[3]) * (1.f/128.f);
        stats[1] = sqrtf(var + 1e-5f);
    }
    __syncthreads();
    out[(size_t)idx * CH + tid] = d / stats[1] * gn[tid] + betan[tid];
}

// ======================================================================
// Kernel 3: edge features (39 per edge), one thread per edge, f-major out
// ======================================================================
__global__ void __launch_bounds__(256)
efeat_kernel(const float* __restrict__ X)
{
    const int e = blockIdx.x * 256 + threadIdx.x;
    if (e >= NEDGE) return;
    const int bi = e / KK;                 // b*LL + i
    const int b = bi / LL, i = bi % LL;
    const int j = g_eidx[e];
    const float D = g_dnb[e];

    float F[39];

    const float d = (float)(j - i);
    const float cfac = -0.5756462732485115f;   // -(log(10000)/16)
    #pragma unroll
    for (int m = 0; m < 8; m++) {
        float freq = expf((float)(2*m) * cfac);
        float a = d * freq;
        F[m]     = cosf(a);
        F[8 + m] = sinf(a);
    }

    #pragma unroll
    for (int m = 0; m < 16; m++) {
        float mu = (float)m * (20.0f / 15.0f);
        float t = (D - mu) / 1.25f;
        F[16 + m] = expf(-(t * t));
    }

    const float* Oi = g_O + (size_t)bi * 9;
    const float* Oj = g_O + ((size_t)b*LL + j) * 9;
    float oi[9], oj[9];
    #pragma unroll
    for (int t = 0; t < 9; t++) { oi[t] = Oi[t]; oj[t] = Oj[t]; }
    const float* Xi = X + (size_t)bi * 12 + 3;
    const float* Xj = X + ((size_t)b*LL + j) * 12 + 3;
    float dX[3] = {Xj[0]-Xi[0], Xj[1]-Xi[1], Xj[2]-Xi[2]};
    float du[3] = { oi[0]*dX[0] + oi[1]*dX[1] + oi[2]*dX[2],
                    oi[3]*dX[0] + oi[4]*dX[1] + oi[5]*dX[2],
                    oi[6]*dX[0] + oi[7]*dX[1] + oi[8]*dX[2] };
    norm3(du);
    F[32] = du[0]; F[33] = du[1]; F[34] = du[2];

    float R[3][3];
    #pragma unroll
    for (int r = 0; r < 3; r++)
        #pragma unroll
        for (int c = 0; c < 3; c++)
            R[r][c] = oi[r]*oj[c] + oi[3+r]*oj[3+c] + oi[6+r]*oj[6+c];

    float Rxx = R[0][0], Ryy = R[1][1], Rzz = R[2][2];
    float m0 = 0.5f * sqrtf(fabsf((1.f + ( Rxx - Ryy - Rzz)) + 1e-10f));
    float m1 = 0.5f * sqrtf(fabsf((1.f + (-Rxx + Ryy - Rzz)) + 1e-10f));
    float m2 = 0.5f * sqrtf(fabsf((1.f + (-Rxx - Ryy + Rzz)) + 1e-10f));
    float qx = sgnf(R[2][1] - R[1][2]) * m0;
    float qy = sgnf(R[0][2] - R[2][0]) * m1;
    float qz = sgnf(R[1][0] - R[0][1]) * m2;
    float qw = sqrtf(fmaxf(1.f + Rxx + Ryy + Rzz, 0.f)) * 0.5f;
    float qn = sqrtf(qx*qx + qy*qy + qz*qz + qw*qw);
    qn = fmaxf(qn, 1e-12f);
    F[35] = qx/qn; F[36] = qy/qn; F[37] = qz/qn; F[38] = qw/qn;

    #pragma unroll
    for (int f = 0; f < 39; f++) g_feat[(size_t)f * NEDGE + e] = F[f];
}

// ======================================================================
// Kernel 4: edge GEMM ([491520 x 39] @ [39 x 128]) + bias + layernorm.
// 128 threads/block, TILE=32 edges.
//   half h = t>>6 owns edges [h*16, h*16+16); u = t&63 owns channels (u, u+64).
// Weights pre-paired in shared (1 LDS.64/f); FFMA2 mainloop; low reg pressure.
// ======================================================================
#define TILE 32
__global__ void __launch_bounds__(128)
egemm_kernel(const float* __restrict__ We, const float* __restrict__ be,
             const float* __restrict__ ge, const float* __restrict__ betae,
             float* __restrict__ out)
{
    const int e0 = blockIdx.x * TILE;
    const int t  = threadIdx.x;
    const int h  = t >> 6;            // edge half: 0 or 1
    const int u  = t & 63;            // channel pair id
    const int c0 = u, c1 = u + 64;

    __shared__ __align__(16) float ft[39][TILE];            // 4,992 B
    __shared__ __align__(16) unsigned long long W2[39][64]; // 19,968 B
    __shared__ float outs[TILE][CH];                        // 16,384 B
    __shared__ float mu_s[TILE], irs_s[TILE];

    // pack weights: W2[f][u] = (W[f][u], W[f][u+64])
    for (int idx = t; idx < 39*64; idx += 128) {
        int f = idx >> 6, k = idx & 63;
        W2[f][k] = pack2(We[f*CH + k], We[f*CH + k + 64]);
    }
    // features for this tile (f-major, coalesced)
    for (int idx = t; idx < 39*TILE; idx += 128) {
        int f = idx >> 5, e = idx & 31;
        ft[f][e] = g_feat[(size_t)f * NEDGE + e0 + e];
    }
    __syncthreads();

    const float bias0 = be[c0], bias1 = be[c1];

    // acc0[m] = (edge h*16+2m, edge h*16+2m+1) for channel c0; acc1 for c1
    unsigned long long acc0[8], acc1[8];
    const unsigned long long bi0 = pack2(bias0, bias0);
    const unsigned long long bi1 = pack2(bias1, bias1);
    #pragma unroll
    for (int m = 0; m < 8; m++) { acc0[m] = bi0; acc1[m] = bi1; }

    #pragma unroll
    for (int f = 0; f < 39; f++) {
        float2 wp = unpack2(W2[f][u]);
        const unsigned long long wa = pack2(wp.x, wp.x);
        const unsigned long long wb = pack2(wp.y, wp.y);
        // 16 floats (edges h*16..h*16+15) = 2 x LDS.128
        const ulonglong2* row = reinterpret_cast<const ulonglong2*>(&ft[f][h*16]);
        ulonglong2 v0 = row[0];
        ulonglong2 v1 = row[1];
        fma2(acc0[0], wa, v0.x);  fma2(acc1[0], wb, v0.x);
        fma2(acc0[1], wa, v0.y);  fma2(acc1[1], wb, v0.y);
        fma2(acc0[2], wa, v1.x);  fma2(acc1[2], wb, v1.x);
        fma2(acc0[3], wa, v1.y);  fma2(acc1[3], wb, v1.y);
        const ulonglong2* row2 = reinterpret_cast<const ulonglong2*>(&ft[f][h*16 + 8]);
        ulonglong2 v2 = row2[0];
        ulonglong2 v3 = row2[1];
        fma2(acc0[4], wa, v2.x);  fma2(acc1[4], wb, v2.x);
        fma2(acc0[5], wa, v2.y);  fma2(acc1[5], wb, v2.y);
        fma2(acc0[6], wa, v3.x);  fma2(acc1[6], wb, v3.x);
        fma2(acc0[7], wa, v3.y);  fma2(acc1[7], wb, v3.y);
    }

    // scatter accumulators to outs for the LN reduction
    #pragma unroll
    for (int m = 0; m < 8; m++) {
        float2 p0 = unpack2(acc0[m]);
        float2 p1 = unpack2(acc1[m]);
        int ea = h*16 + 2*m, eb = ea + 1;
        outs[ea][c0] = p0.x;
        outs[eb][c0] = p0.y;
        outs[ea][c1] = p1.x;
        outs[eb][c1] = p1.y;
    }
    __syncthreads();

    // layernorm stats: 4 warps, 8 edges each
    const int wwid = t >> 5, lane = t & 31;
    #pragma unroll
    for (int q = 0; q < 8; q++) {
        int e = wwid * 8 + q;
        float v0 = outs[e][lane], v1 = outs[e][lane+32];
        float v2 = outs[e][lane+64], v3 = outs[e][lane+96];
        float s = v0 + v1 + v2 + v3;
        #pragma unroll
        for (int o = 16; o > 0; o >>= 1) s += __shfl_xor_sync(0xffffffffu, s, o);
        float mu = s * (1.f/128.f);
        float d0 = v0-mu, d1 = v1-mu, d2 = v2-mu, d3 = v3-mu;
        float s2 = d0*d0 + d1*d1 + d2*d2 + d3*d3;
        #pragma unroll
        for (int o = 16; o > 0; o >>= 1) s2 += __shfl_xor_sync(0xffffffffu, s2, o);
        if (lane == 0) {
            mu_s[e] = mu;
            irs_s[e] = 1.f / sqrtf(s2 * (1.f/128.f) + 1e-5f);
        }
    }
    __syncthreads();

    const float gg0 = ge[c0], gg1 = ge[c1];
    const float bb0 = betae[c0], bb1 = betae[c1];
    const size_t base = E_OFF + (size_t)e0 * CH;
    #pragma unroll
    for (int m = 0; m < 8; m++) {
        float2 p0 = unpack2(acc0[m]);
        float2 p1 = unpack2(acc1[m]);
        int ea = h*16 + 2*m, eb = ea + 1;
        float mua = mu_s[ea], ia = irs_s[ea];
        float mub = mu_s[eb], ib = irs_s[eb];
        out[base + (size_t)ea * CH + c0] = (p0.x - mua) * ia * gg0 + bb0;
        out[base + (size_t)eb * CH + c0] = (p0.y - mub) * ib * gg0 + bb0;
        out[base + (size_t)ea * CH + c1] = (p1.x - mua) * ia * gg1 + bb1;
        out[base + (size_t)eb * CH + c1] = (p1.y - mub) * ib * gg1 + bb1;
    }
}

// ======================================================================
extern "C" void kernel_launch(void* const* d_in, const int* in_sizes, int n_in,
                              void* d_out, int out_size)
{
    const float* X      = (const float*)d_in[0];
    // d_in[1] = mask (all ones; unused)
    const float* W_node = (const float*)d_in[2];
    const float* b_node = (const float*)d_in[3];
    const float* g_node = (const float*)d_in[4];
    const float* be_node= (const float*)d_in[5];
    const float* W_edge = (const float*)d_in[6];
    const float* b_edge = (const float*)d_in[7];
    const float* g_edge = (const float*)d_in[8];
    const float* be_edge= (const float*)d_in[9];
    float* out = (float*)d_out;

    knn_kernel<<<dim3(LL/16, NB), 512>>>(X, out);
    node_kernel<<<NB*LL, 128>>>(X, W_node, b_node, g_node, be_node, out);
    efeat_kernel<<<(NEDGE + 255)/256, 256>>>(X);
    egemm_kernel<<<NEDGE/TILE, 128>>>(W_edge, b_edge, g_edge, be_edge, out);
}

// round 5
// speedup vs baseline: 1.4969x; 1.1803x over previous
#include <cuda_runtime.h>
#include <cstdint>
#include <cstddef>

#define NB 8
#define LL 2048
#define KK 30
#define CH 128
#define NEDGE (NB*LL*KK)   // 491520

static constexpr size_t V_SIZE = (size_t)NB * LL * CH;           // 2,097,152
static constexpr size_t E_SIZE = (size_t)NB * LL * KK * CH;      // 62,914,560
static constexpr size_t E_OFF  = V_SIZE;
static constexpr size_t I_OFF  = V_SIZE + E_SIZE;

// -------- scratch (device globals; no allocations allowed) --------
__device__ float g_dnb[NB*LL*KK];      // sorted neighbor distances
__device__ int   g_eidx[NB*LL*KK];     // sorted neighbor indices
__device__ float g_O[NB*LL*9];         // per-residue orientation frames
__device__ float g_feat[39*NEDGE];     // edge features, f-major
__device__ unsigned long long g_W2[39*64];  // paired weights (w_u, w_{u+64})

// ---------------- small helpers ----------------
__device__ __forceinline__ float dot3(const float* a, const float* b) {
    return a[0]*b[0] + a[1]*b[1] + a[2]*b[2];
}
__device__ __forceinline__ void cross3(const float* a, const float* b, float* o) {
    o[0] = a[1]*b[2] - a[2]*b[1];
    o[1] = a[2]*b[0] - a[0]*b[2];
    o[2] = a[0]*b[1] - a[1]*b[0];
}
__device__ __forceinline__ void norm3(float* v) {
    float n = sqrtf(v[0]*v[0] + v[1]*v[1] + v[2]*v[2]);
    n = fmaxf(n, 1e-12f);
    v[0] /= n; v[1] /= n; v[2] /= n;
}
__device__ __forceinline__ float sgnf(float v) {
    return (v > 0.f) ? 1.f : ((v < 0.f) ? -1.f : 0.f);
}

// packed fp32x2 ops (sm_103a)
__device__ __forceinline__ unsigned long long pack2(float x, float y) {
    unsigned long long r;
    asm("mov.b64 %0, {%1, %2};" : "=l"(r) : "f"(x), "f"(y));
    return r;
}
__device__ __forceinline__ float2 unpack2(unsigned long long v) {
    float2 r;
    asm("mov.b64 {%0, %1}, %2;" : "=f"(r.x), "=f"(r.y) : "l"(v));
    return r;
}
__device__ __forceinline__ void fma2(unsigned long long& d,
                                     unsigned long long a, unsigned long long b) {
    asm("fma.rn.f32x2 %0, %1, %2, %0;" : "+l"(d) : "l"(a), "l"(b));
}

// ======================================================================
// Kernel 1: exact KNN matching jax.lax.top_k(-D) bit-for-bit.
// ======================================================================
__global__ void __launch_bounds__(512)
knn_kernel(const float* __restrict__ X, float* __restrict__ out)
{
    __shared__ float4 pts[LL];                 // 32 KB
    const int b = blockIdx.y;
    const float* Xb = X + (size_t)b * LL * 12;

    for (int t = threadIdx.x; t < LL; t += blockDim.x) {
        pts[t] = make_float4(Xb[t*12 + 3], Xb[t*12 + 4], Xb[t*12 + 5], 0.f);
    }
    __syncthreads();

    const int wid  = threadIdx.x >> 5;
    const int lane = threadIdx.x & 31;
    const int i = blockIdx.x * 16 + wid;       // query index
    const float4 q = pts[i];
    const unsigned FULL = 0xffffffffu;

    auto exact_key = [&](float px, float py, float pz, int j) -> unsigned long long {
        float dx = __fsub_rn(px, q.x);
        float dy = __fsub_rn(py, q.y);
        float dz = __fsub_rn(pz, q.z);
        float d2 = __fadd_rn(__fadd_rn(__fmul_rn(dx,dx), __fmul_rn(dy,dy)),
                             __fmul_rn(dz,dz));
        float D  = sqrtf(__fadd_rn(d2, 1e-6f));   // sqrt.rn — matches XLA
        return ((unsigned long long)__float_as_uint(D) << 32) | (unsigned)j;
    };

    float4 p = pts[lane];
    unsigned long long cur = exact_key(p.x, p.y, p.z, lane);

    unsigned long long thr;
    float thr_d2;
    auto update_thr = [&]() {
        unsigned hi = __reduce_max_sync(FULL, (unsigned)(cur >> 32));
        unsigned lo = __reduce_max_sync(FULL,
                          ((unsigned)(cur >> 32) == hi) ? (unsigned)cur : 0u);
        thr = ((unsigned long long)hi << 32) | lo;
        float D = __uint_as_float(hi);
        thr_d2 = D * D * 1.00002f;     // conservative vs fma/rn/sqrt ulps
    };
    update_thr();

    for (int t = 1; t < LL/32; t++) {
        const int j = t*32 + lane;
        p = pts[j];
        float dx = p.x - q.x, dy = p.y - q.y, dz = p.z - q.z;
        float d2c = fmaf(dx, dx, fmaf(dy, dy, dz*dz));
        bool pass = d2c <= thr_d2;
        unsigned bal = __ballot_sync(FULL, pass);
        if (!bal) continue;                       // warp-uniform
        unsigned long long kk = pass ? exact_key(p.x, p.y, p.z, j) : ~0ull;
        do {
            int s = __ffs(bal) - 1;
            bal &= bal - 1;
            unsigned long long bk = __shfl_sync(FULL, kk, s);
            if (bk < thr) {                       // warp-uniform
                unsigned m = __ballot_sync(FULL, cur == thr);  // keys unique
                if (lane == (__ffs(m) - 1)) cur = bk;
                update_thr();
            }
        } while (bal);
    }

    // bitonic sort 32 keys across the warp, ascending
    #pragma unroll
    for (int k = 2; k <= 32; k <<= 1) {
        #pragma unroll
        for (int j = k >> 1; j >= 1; j >>= 1) {
            unsigned long long ok = __shfl_xor_sync(FULL, cur, j);
            bool up    = ((lane & k) == 0);
            bool lower = ((lane & j) == 0);
            bool mineLess = (cur < ok);
            bool takeOther = up ? (lower ? !mineLess : mineLess)
                                : (lower ? mineLess : !mineLess);
            if (takeOther) cur = ok;
        }
    }

    if (lane < KK) {
        int e = (b*LL + i)*KK + lane;
        int nidx = (int)(cur & 0xffffffffu);
        g_dnb[e]  = __uint_as_float((unsigned)(cur >> 32));
        g_eidx[e] = nidx;
        out[I_OFF + (size_t)e] = (float)nidx;
    }
}

// ======================================================================
// Kernel 2: node features (dihedrals -> 6) @ W_node + LN; also builds O.
// ======================================================================
__global__ void __launch_bounds__(128)
node_kernel(const float* __restrict__ X,
            const float* __restrict__ Wn, const float* __restrict__ bn,
            const float* __restrict__ gn, const float* __restrict__ betan,
            float* __restrict__ out)
{
    const int idx = blockIdx.x;          // b*LL + i
    const int b = idx / LL, i = idx % LL;
    const float* Xb = X + (size_t)b * LL * 12;

    __shared__ float feat[6];
    __shared__ float red[4];
    __shared__ float stats[2];

    const int tid = threadIdx.x;
    const int wid = tid >> 5, lane = tid & 31;

    if (tid < 3) {
        int t = 3*i + tid - 1;
        float ang = 0.f;
        if (t >= 0 && t <= 3*LL - 4) {
            float P[4][3];
            #pragma unroll
            for (int a = 0; a < 4; a++) {
                int g = t + a;
                const float* ptr = Xb + (g/3)*12 + (g%3)*3;
                P[a][0] = ptr[0]; P[a][1] = ptr[1]; P[a][2] = ptr[2];
            }
            float u2[3], u1[3], u0[3], n2[3], n1[3];
            #pragma unroll
            for (int c = 0; c < 3; c++) {
                u2[c] = P[1][c] - P[0][c];
                u1[c] = P[2][c] - P[1][c];
                u0[c] = P[3][c] - P[2][c];
            }
            norm3(u2); norm3(u1); norm3(u0);
            cross3(u2, u1, n2); norm3(n2);
            cross3(u1, u0, n1); norm3(n1);
            float cd = dot3(n2, n1);
            cd = fminf(fmaxf(cd, -1.f + 1e-7f), 1.f - 1e-7f);
            ang = sgnf(dot3(u2, n1)) * acosf(cd);
        }
        feat[tid]     = cosf(ang);
        feat[tid + 3] = sinf(ang);
    }
    if (tid == 3) {
        const float* pr = Xb + i*12;
        float N[3]  = {pr[0], pr[1], pr[2]};
        float CA[3] = {pr[3], pr[4], pr[5]};
        float C[3]  = {pr[6], pr[7], pr[8]};
        float nca[3], cac[3];
        #pragma unroll
        for (int c = 0; c < 3; c++) { nca[c] = CA[c] - N[c]; cac[c] = C[c] - CA[c]; }
        norm3(nca); norm3(cac);
        float n1[3]; cross3(nca, cac, n1); norm3(n1);
        float bb[3];
        #pragma unroll
        for (int c = 0; c < 3; c++) bb[c] = cac[c] - nca[c];
        norm3(bb);
        float xx[3]; cross3(bb, n1, xx); norm3(xx);
        float* o = g_O + (size_t)idx * 9;
        o[0]=bb[0]; o[1]=bb[1]; o[2]=bb[2];
        o[3]=n1[0]; o[4]=n1[1]; o[5]=n1[2];
        o[6]=xx[0]; o[7]=xx[1]; o[8]=xx[2];
    }
    __syncthreads();

    float acc = bn[tid];
    #pragma unroll
    for (int f = 0; f < 6; f++) acc += feat[f] * Wn[f*CH + tid];

    float s = acc;
    #pragma unroll
    for (int o = 16; o > 0; o >>= 1) s += __shfl_down_sync(0xffffffffu, s, o);
    if (lane == 0) red[wid] = s;
    __syncthreads();
    if (tid == 0) stats[0] = (red[0] + red[1] + red[2] + red[3]) * (1.f/128.f);
    __syncthreads();
    float d = acc - stats[0];
    float s2 = d * d;
    #pragma unroll
    for (int o = 16; o > 0; o >>= 1) s2 += __shfl_down_sync(0xffffffffu, s2, o);
    if (lane == 0) red[wid] = s2;
    __syncthreads();
    if (tid == 0) {
        float var = (red[0] + red[1] + red[2] + red[3]) * (1.f/128.f);
        stats[1] = sqrtf(var + 1e-5f);
    }
    __syncthreads();
    out[(size_t)idx * CH + tid] = d / stats[1] * gn[tid] + betan[tid];
}

// ======================================================================
// Kernel 3: edge features (39 per edge), one thread per edge, f-major out
// ======================================================================
__global__ void __launch_bounds__(256)
efeat_kernel(const float* __restrict__ X)
{
    const int e = blockIdx.x * 256 + threadIdx.x;
    if (e >= NEDGE) return;
    const int bi = e / KK;                 // b*LL + i
    const int b = bi / LL, i = bi % LL;
    const int j = g_eidx[e];
    const float D = g_dnb[e];

    float F[39];

    const float d = (float)(j - i);
    const float cfac = -0.5756462732485115f;   // -(log(10000)/16)
    #pragma unroll
    for (int m = 0; m < 8; m++) {
        float freq = expf((float)(2*m) * cfac);
        float a = d * freq;
        F[m]     = cosf(a);
        F[8 + m] = sinf(a);
    }

    #pragma unroll
    for (int m = 0; m < 16; m++) {
        float mu = (float)m * (20.0f / 15.0f);
        float t = (D - mu) / 1.25f;
        F[16 + m] = expf(-(t * t));
    }

    const float* Oi = g_O + (size_t)bi * 9;
    const float* Oj = g_O + ((size_t)b*LL + j) * 9;
    float oi[9], oj[9];
    #pragma unroll
    for (int t = 0; t < 9; t++) { oi[t] = Oi[t]; oj[t] = Oj[t]; }
    const float* Xi = X + (size_t)bi * 12 + 3;
    const float* Xj = X + ((size_t)b*LL + j) * 12 + 3;
    float dX[3] = {Xj[0]-Xi[0], Xj[1]-Xi[1], Xj[2]-Xi[2]};
    float du[3] = { oi[0]*dX[0] + oi[1]*dX[1] + oi[2]*dX[2],
                    oi[3]*dX[0] + oi[4]*dX[1] + oi[5]*dX[2],
                    oi[6]*dX[0] + oi[7]*dX[1] + oi[8]*dX[2] };
    norm3(du);
    F[32] = du[0]; F[33] = du[1]; F[34] = du[2];

    float R[3][3];
    #pragma unroll
    for (int r = 0; r < 3; r++)
        #pragma unroll
        for (int c = 0; c < 3; c++)
            R[r][c] = oi[r]*oj[c] + oi[3+r]*oj[3+c] + oi[6+r]*oj[6+c];

    float Rxx = R[0][0], Ryy = R[1][1], Rzz = R[2][2];
    float m0 = 0.5f * sqrtf(fabsf((1.f + ( Rxx - Ryy - Rzz)) + 1e-10f));
    float m1 = 0.5f * sqrtf(fabsf((1.f + (-Rxx + Ryy - Rzz)) + 1e-10f));
    float m2 = 0.5f * sqrtf(fabsf((1.f + (-Rxx - Ryy + Rzz)) + 1e-10f));
    float qx = sgnf(R[2][1] - R[1][2]) * m0;
    float qy = sgnf(R[0][2] - R[2][0]) * m1;
    float qz = sgnf(R[1][0] - R[0][1]) * m2;
    float qw = sqrtf(fmaxf(1.f + Rxx + Ryy + Rzz, 0.f)) * 0.5f;
    float qn = sqrtf(qx*qx + qy*qy + qz*qz + qw*qw);
    qn = fmaxf(qn, 1e-12f);
    F[35] = qx/qn; F[36] = qy/qn; F[37] = qz/qn; F[38] = qw/qn;

    #pragma unroll
    for (int f = 0; f < 39; f++) g_feat[(size_t)f * NEDGE + e] = F[f];
}

// ======================================================================
// Weight pre-pack: g_W2[f*64+u] = (We[f][u], We[f][u+64])
// ======================================================================
__global__ void packw_kernel(const float* __restrict__ We)
{
    int idx = blockIdx.x * 256 + threadIdx.x;
    if (idx < 39*64) {
        int f = idx >> 6, u = idx & 63;
        g_W2[idx] = pack2(We[f*CH + u], We[f*CH + u + 64]);
    }
}

// ======================================================================
// Kernel 4: edge GEMM + bias + LN.
// 256 threads/block, TILE=32 edges. Thread (h=t>>6, u=t&63):
//   edges [h*8, h*8+8), channel pair (u, u+64).
// acc[e] = (out_u, out_{u+64}) as f32x2; weights pre-paired (no packs);
// features duplicated in smem so both FFMA2 operands load directly.
// ======================================================================
#define TILE 32
__global__ void __launch_bounds__(256)
egemm_kernel(const float* __restrict__ be,
             const float* __restrict__ ge, const float* __restrict__ betae,
             float* __restrict__ out)
{
    const int e0 = blockIdx.x * TILE;
    const int t  = threadIdx.x;
    const int h  = t >> 6;            // 0..3
    const int u  = t & 63;

    __shared__ __align__(16) unsigned long long W2s[39*64];   // 19,968 B
    __shared__ __align__(16) unsigned long long ftd[39*32];   //  9,984 B
    __shared__ float mu_s[TILE], irs_s[TILE];
    __shared__ float red[2][TILE];

    // copy pre-paired weights (LDG.128 -> STS.128)
    {
        const ulonglong2* src = reinterpret_cast<const ulonglong2*>(g_W2);
        ulonglong2* dst = reinterpret_cast<ulonglong2*>(W2s);
        #pragma unroll
        for (int k = 0; k < 5; k++) {
            int idx = t + k*256;
            if (idx < 39*32) dst[idx] = src[idx];
        }
    }
    // load features for this tile, duplicated: ftd[f*32+e] = (F,F)
    #pragma unroll
    for (int k = 0; k < 5; k++) {
        int idx = t + k*256;
        if (idx < 39*TILE) {
            int f = idx >> 5, e = idx & 31;
            float v = g_feat[(size_t)f * NEDGE + e0 + e];
            ftd[idx] = pack2(v, v);
        }
    }
    __syncthreads();

    unsigned long long acc[8];
    {
        unsigned long long bi = pack2(be[u], be[u + 64]);
        #pragma unroll
        for (int m = 0; m < 8; m++) acc[m] = bi;
    }

    #pragma unroll
    for (int f = 0; f < 39; f++) {
        unsigned long long w = W2s[f*64 + u];                       // LDS.64
        const ulonglong2* fp =
            reinterpret_cast<const ulonglong2*>(&ftd[f*32 + h*8]);  // broadcast
        ulonglong2 v0 = fp[0];
        ulonglong2 v1 = fp[1];
        ulonglong2 v2 = fp[2];
        ulonglong2 v3 = fp[3];
        fma2(acc[0], w, v0.x);  fma2(acc[1], w, v0.y);
        fma2(acc[2], w, v1.x);  fma2(acc[3], w, v1.y);
        fma2(acc[4], w, v2.x);  fma2(acc[5], w, v2.y);
        fma2(acc[6], w, v3.x);  fma2(acc[7], w, v3.y);
    }

    // ---- LN stats, two-pass from registers ----
    const int lane = t & 31;
    const int par  = (t >> 5) & 1;     // which 32-channel half of u-range

    float s[8];
    #pragma unroll
    for (int m = 0; m < 8; m++) {
        float2 p = unpack2(acc[m]);
        s[m] = p.x + p.y;
    }
    #pragma unroll
    for (int m = 0; m < 8; m++)
        #pragma unroll
        for (int o = 16; o > 0; o >>= 1)
            s[m] += __shfl_xor_sync(0xffffffffu, s[m], o);
    if (lane == 0) {
        #pragma unroll
        for (int m = 0; m < 8; m++) red[par][h*8 + m] = s[m];
    }
    __syncthreads();
    if (t < TILE) mu_s[t] = (red[0][t] + red[1][t]) * (1.f/128.f);
    __syncthreads();

    #pragma unroll
    for (int m = 0; m < 8; m++) {
        float mu = mu_s[h*8 + m];
        float2 p = unpack2(acc[m]);
        float d0 = p.x - mu, d1 = p.y - mu;
        s[m] = d0*d0 + d1*d1;
    }
    #pragma unroll
    for (int m = 0; m < 8; m++)
        #pragma unroll
        for (int o = 16; o > 0; o >>= 1)
            s[m] += __shfl_xor_sync(0xffffffffu, s[m], o);
    if (lane == 0) {
        #pragma unroll
        for (int m = 0; m < 8; m++) red[par][h*8 + m] = s[m];
    }
    __syncthreads();
    if (t < TILE)
        irs_s[t] = 1.f / sqrtf((red[0][t] + red[1][t]) * (1.f/128.f) + 1e-5f);
    __syncthreads();

    const float gg0 = ge[u], gg1 = ge[u + 64];
    const float bb0 = betae[u], bb1 = betae[u + 64];
    const size_t base = E_OFF + (size_t)e0 * CH;
    #pragma unroll
    for (int m = 0; m < 8; m++) {
        int e = h*8 + m;
        float mu = mu_s[e], is = irs_s[e];
        float2 p = unpack2(acc[m]);
        out[base + (size_t)e * CH + u]      = (p.x - mu) * is * gg0 + bb0;
        out[base + (size_t)e * CH + u + 64] = (p.y - mu) * is * gg1 + bb1;
    }
}

// ======================================================================
extern "C" void kernel_launch(void* const* d_in, const int* in_sizes, int n_in,
                              void* d_out, int out_size)
{
    const float* X      = (const float*)d_in[0];
    // d_in[1] = mask (all ones; unused)
    const float* W_node = (const float*)d_in[2];
    const float* b_node = (const float*)d_in[3];
    const float* g_node = (const float*)d_in[4];
    const float* be_node= (const float*)d_in[5];
    const float* W_edge = (const float*)d_in[6];
    const float* b_edge = (const float*)d_in[7];
    const float* g_edge = (const float*)d_in[8];
    const float* be_edge= (const float*)d_in[9];
    float* out = (float*)d_out;

    knn_kernel<<<dim3(LL/16, NB), 512>>>(X, out);
    node_kernel<<<NB*LL, 128>>>(X, W_node, b_node, g_node, be_node, out);
    efeat_kernel<<<(NEDGE + 255)/256, 256>>>(X);
    packw_kernel<<<(39*64 + 255)/256, 256>>>(W_edge);
    egemm_kernel<<<NEDGE/TILE, 256>>>(b_edge, g_edge, be_edge, out);
}

// round 6
// speedup vs baseline: 1.5680x; 1.0475x over previous
#include <cuda_runtime.h>
#include <cstdint>
#include <cstddef>

#define NB 8
#define LL 2048
#define KK 30
#define CH 128
#define NEDGE (NB*LL*KK)   // 491520

static constexpr size_t V_SIZE = (size_t)NB * LL * CH;           // 2,097,152
static constexpr size_t E_SIZE = (size_t)NB * LL * KK * CH;      // 62,914,560
static constexpr size_t E_OFF  = V_SIZE;
static constexpr size_t I_OFF  = V_SIZE + E_SIZE;

// -------- scratch (device globals; no allocations allowed) --------
__device__ float g_dnb[NB*LL*KK];      // sorted neighbor distances
__device__ int   g_eidx[NB*LL*KK];     // sorted neighbor indices
__device__ float g_O[NB*LL*9];         // per-residue orientation frames
__device__ float g_feat[39*NEDGE];     // edge features, f-major
__device__ unsigned long long g_W2[39*64];  // paired weights (w_u, w_{u+64})

// ---------------- small helpers ----------------
__device__ __forceinline__ float dot3(const float* a, const float* b) {
    return a[0]*b[0] + a[1]*b[1] + a[2]*b[2];
}
__device__ __forceinline__ void cross3(const float* a, const float* b, float* o) {
    o[0] = a[1]*b[2] - a[2]*b[1];
    o[1] = a[2]*b[0] - a[0]*b[2];
    o[2] = a[0]*b[1] - a[1]*b[0];
}
__device__ __forceinline__ void norm3(float* v) {
    float n = sqrtf(v[0]*v[0] + v[1]*v[1] + v[2]*v[2]);
    n = fmaxf(n, 1e-12f);
    v[0] /= n; v[1] /= n; v[2] /= n;
}
__device__ __forceinline__ float sgnf(float v) {
    return (v > 0.f) ? 1.f : ((v < 0.f) ? -1.f : 0.f);
}

// packed fp32x2 ops (sm_103a)
__device__ __forceinline__ unsigned long long pack2(float x, float y) {
    unsigned long long r;
    asm("mov.b64 %0, {%1, %2};" : "=l"(r) : "f"(x), "f"(y));
    return r;
}
__device__ __forceinline__ float2 unpack2(unsigned long long v) {
    float2 r;
    asm("mov.b64 {%0, %1}, %2;" : "=f"(r.x), "=f"(r.y) : "l"(v));
    return r;
}
__device__ __forceinline__ void fma2(unsigned long long& d,
                                     unsigned long long a, unsigned long long b) {
    asm("fma.rn.f32x2 %0, %1, %2, %0;" : "+l"(d) : "l"(a), "l"(b));
}

// ======================================================================
// Kernel 1: exact KNN matching jax.lax.top_k(-D) bit-for-bit.
// ======================================================================
__global__ void __launch_bounds__(512)
knn_kernel(const float* __restrict__ X, float* __restrict__ out)
{
    __shared__ float4 pts[LL];                 // 32 KB
    const int b = blockIdx.y;
    const float* Xb = X + (size_t)b * LL * 12;

    for (int t = threadIdx.x; t < LL; t += blockDim.x) {
        pts[t] = make_float4(Xb[t*12 + 3], Xb[t*12 + 4], Xb[t*12 + 5], 0.f);
    }
    __syncthreads();

    const int wid  = threadIdx.x >> 5;
    const int lane = threadIdx.x & 31;
    const int i = blockIdx.x * 16 + wid;       // query index
    const float4 q = pts[i];
    const unsigned FULL = 0xffffffffu;

    auto exact_key = [&](float px, float py, float pz, int j) -> unsigned long long {
        float dx = __fsub_rn(px, q.x);
        float dy = __fsub_rn(py, q.y);
        float dz = __fsub_rn(pz, q.z);
        float d2 = __fadd_rn(__fadd_rn(__fmul_rn(dx,dx), __fmul_rn(dy,dy)),
                             __fmul_rn(dz,dz));
        float D  = sqrtf(__fadd_rn(d2, 1e-6f));   // sqrt.rn — matches XLA
        return ((unsigned long long)__float_as_uint(D) << 32) | (unsigned)j;
    };

    float4 p = pts[lane];
    unsigned long long cur = exact_key(p.x, p.y, p.z, lane);

    unsigned long long thr;
    float thr_d2;
    auto update_thr = [&]() {
        unsigned hi = __reduce_max_sync(FULL, (unsigned)(cur >> 32));
        unsigned lo = __reduce_max_sync(FULL,
                          ((unsigned)(cur >> 32) == hi) ? (unsigned)cur : 0u);
        thr = ((unsigned long long)hi << 32) | lo;
        float D = __uint_as_float(hi);
        thr_d2 = D * D * 1.00002f;     // conservative vs fma/rn/sqrt ulps
    };
    update_thr();

    for (int t = 1; t < LL/32; t++) {
        const int j = t*32 + lane;
        p = pts[j];
        float dx = p.x - q.x, dy = p.y - q.y, dz = p.z - q.z;
        float d2c = fmaf(dx, dx, fmaf(dy, dy, dz*dz));
        bool pass = d2c <= thr_d2;
        unsigned bal = __ballot_sync(FULL, pass);
        if (!bal) continue;                       // warp-uniform
        unsigned long long kk = pass ? exact_key(p.x, p.y, p.z, j) : ~0ull;
        do {
            int s = __ffs(bal) - 1;
            bal &= bal - 1;
            unsigned long long bk = __shfl_sync(FULL, kk, s);
            if (bk < thr) {                       // warp-uniform
                unsigned m = __ballot_sync(FULL, cur == thr);  // keys unique
                if (lane == (__ffs(m) - 1)) cur = bk;
                update_thr();
            }
        } while (bal);
    }

    // bitonic sort 32 keys across the warp, ascending
    #pragma unroll
    for (int k = 2; k <= 32; k <<= 1) {
        #pragma unroll
        for (int j = k >> 1; j >= 1; j >>= 1) {
            unsigned long long ok = __shfl_xor_sync(FULL, cur, j);
            bool up    = ((lane & k) == 0);
            bool lower = ((lane & j) == 0);
            bool mineLess = (cur < ok);
            bool takeOther = up ? (lower ? !mineLess : mineLess)
                                : (lower ? mineLess : !mineLess);
            if (takeOther) cur = ok;
        }
    }

    if (lane < KK) {
        int e = (b*LL + i)*KK + lane;
        int nidx = (int)(cur & 0xffffffffu);
        g_dnb[e]  = __uint_as_float((unsigned)(cur >> 32));
        g_eidx[e] = nidx;
        out[I_OFF + (size_t)e] = (float)nidx;
    }
}

// ======================================================================
// Kernel 2: node features (dihedrals -> 6) @ W_node + LN; also builds O.
// ======================================================================
__global__ void __launch_bounds__(128)
node_kernel(const float* __restrict__ X,
            const float* __restrict__ Wn, const float* __restrict__ bn,
            const float* __restrict__ gn, const float* __restrict__ betan,
            float* __restrict__ out)
{
    const int idx = blockIdx.x;          // b*LL + i
    const int b = idx / LL, i = idx % LL;
    const float* Xb = X + (size_t)b * LL * 12;

    __shared__ float feat[6];
    __shared__ float red[4];
    __shared__ float stats[2];

    const int tid = threadIdx.x;
    const int wid = tid >> 5, lane = tid & 31;

    if (tid < 3) {
        int t = 3*i + tid - 1;
        float ang = 0.f;
        if (t >= 0 && t <= 3*LL - 4) {
            float P[4][3];
            #pragma unroll
            for (int a = 0; a < 4; a++) {
                int g = t + a;
                const float* ptr = Xb + (g/3)*12 + (g%3)*3;
                P[a][0] = ptr[0]; P[a][1] = ptr[1]; P[a][2] = ptr[2];
            }
            float u2[3], u1[3], u0[3], n2[3], n1[3];
            #pragma unroll
            for (int c = 0; c < 3; c++) {
                u2[c] = P[1][c] - P[0][c];
                u1[c] = P[2][c] - P[1][c];
                u0[c] = P[3][c] - P[2][c];
            }
            norm3(u2); norm3(u1); norm3(u0);
            cross3(u2, u1, n2); norm3(n2);
            cross3(u1, u0, n1); norm3(n1);
            float cd = dot3(n2, n1);
            cd = fminf(fmaxf(cd, -1.f + 1e-7f), 1.f - 1e-7f);
            ang = sgnf(dot3(u2, n1)) * acosf(cd);
        }
        feat[tid]     = cosf(ang);
        feat[tid + 3] = sinf(ang);
    }
    if (tid == 3) {
        const float* pr = Xb + i*12;
        float N[3]  = {pr[0], pr[1], pr[2]};
        float CA[3] = {pr[3], pr[4], pr[5]};
        float C[3]  = {pr[6], pr[7], pr[8]};
        float nca[3], cac[3];
        #pragma unroll
        for (int c = 0; c < 3; c++) { nca[c] = CA[c] - N[c]; cac[c] = C[c] - CA[c]; }
        norm3(nca); norm3(cac);
        float n1[3]; cross3(nca, cac, n1); norm3(n1);
        float bb[3];
        #pragma unroll
        for (int c = 0; c < 3; c++) bb[c] = cac[c] - nca[c];
        norm3(bb);
        float xx[3]; cross3(bb, n1, xx); norm3(xx);
        float* o = g_O + (size_t)idx * 9;
        o[0]=bb[0]; o[1]=bb[1]; o[2]=bb[2];
        o[3]=n1[0]; o[4]=n1[1]; o[5]=n1[2];
        o[6]=xx[0]; o[7]=xx[1]; o[8]=xx[2];
    }
    __syncthreads();

    float acc = bn[tid];
    #pragma unroll
    for (int f = 0; f < 6; f++) acc += feat[f] * Wn[f*CH + tid];

    float s = acc;
    #pragma unroll
    for (int o = 16; o > 0; o >>= 1) s += __shfl_down_sync(0xffffffffu, s, o);
    if (lane == 0) red[wid] = s;
    __syncthreads();
    if (tid == 0) stats[0] = (red[0] + red[1] + red[2] + red[3]) * (1.f/128.f);
    __syncthreads();
    float d = acc - stats[0];
    float s2 = d * d;
    #pragma unroll
    for (int o = 16; o > 0; o >>= 1) s2 += __shfl_down_sync(0xffffffffu, s2, o);
    if (lane == 0) red[wid] = s2;
    __syncthreads();
    if (tid == 0) {
        float var = (red[0] + red[1] + red[2] + red[3]) * (1.f/128.f);
        stats[1] = sqrtf(var + 1e-5f);
    }
    __syncthreads();
    out[(size_t)idx * CH + tid] = d / stats[1] * gn[tid] + betan[tid];
}

// ======================================================================
// Kernel 3: edge features (39 per edge), one thread per edge, f-major out
// ======================================================================
__global__ void __launch_bounds__(256)
efeat_kernel(const float* __restrict__ X)
{
    const int e = blockIdx.x * 256 + threadIdx.x;
    if (e >= NEDGE) return;
    const int bi = e / KK;                 // b*LL + i
    const int b = bi / LL, i = bi % LL;
    const int j = g_eidx[e];
    const float D = g_dnb[e];

    float F[39];

    const float d = (float)(j - i);
    const float cfac = -0.5756462732485115f;   // -(log(10000)/16)
    #pragma unroll
    for (int m = 0; m < 8; m++) {
        float freq = expf((float)(2*m) * cfac);
        float a = d * freq;
        F[m]     = cosf(a);
        F[8 + m] = sinf(a);
    }

    #pragma unroll
    for (int m = 0; m < 16; m++) {
        float mu = (float)m * (20.0f / 15.0f);
        float t = (D - mu) / 1.25f;
        F[16 + m] = expf(-(t * t));
    }

    const float* Oi = g_O + (size_t)bi * 9;
    const float* Oj = g_O + ((size_t)b*LL + j) * 9;
    float oi[9], oj[9];
    #pragma unroll
    for (int t = 0; t < 9; t++) { oi[t] = Oi[t]; oj[t] = Oj[t]; }
    const float* Xi = X + (size_t)bi * 12 + 3;
    const float* Xj = X + ((size_t)b*LL + j) * 12 + 3;
    float dX[3] = {Xj[0]-Xi[0], Xj[1]-Xi[1], Xj[2]-Xi[2]};
    float du[3] = { oi[0]*dX[0] + oi[1]*dX[1] + oi[2]*dX[2],
                    oi[3]*dX[0] + oi[4]*dX[1] + oi[5]*dX[2],
                    oi[6]*dX[0] + oi[7]*dX[1] + oi[8]*dX[2] };
    norm3(du);
    F[32] = du[0]; F[33] = du[1]; F[34] = du[2];

    float R[3][3];
    #pragma unroll
    for (int r = 0; r < 3; r++)
        #pragma unroll
        for (int c = 0; c < 3; c++)
            R[r][c] = oi[r]*oj[c] + oi[3+r]*oj[3+c] + oi[6+r]*oj[6+c];

    float Rxx = R[0][0], Ryy = R[1][1], Rzz = R[2][2];
    float m0 = 0.5f * sqrtf(fabsf((1.f + ( Rxx - Ryy - Rzz)) + 1e-10f));
    float m1 = 0.5f * sqrtf(fabsf((1.f + (-Rxx + Ryy - Rzz)) + 1e-10f));
    float m2 = 0.5f * sqrtf(fabsf((1.f + (-Rxx - Ryy + Rzz)) + 1e-10f));
    float qx = sgnf(R[2][1] - R[1][2]) * m0;
    float qy = sgnf(R[0][2] - R[2][0]) * m1;
    float qz = sgnf(R[1][0] - R[0][1]) * m2;
    float qw = sqrtf(fmaxf(1.f + Rxx + Ryy + Rzz, 0.f)) * 0.5f;
    float qn = sqrtf(qx*qx + qy*qy + qz*qz + qw*qw);
    qn = fmaxf(qn, 1e-12f);
    F[35] = qx/qn; F[36] = qy/qn; F[37] = qz/qn; F[38] = qw/qn;

    #pragma unroll
    for (int f = 0; f < 39; f++) g_feat[(size_t)f * NEDGE + e] = F[f];
}

// ======================================================================
// Weight pre-pack: g_W2[f*64+u] = (We[f][u], We[f][u+64])
// ======================================================================
__global__ void packw_kernel(const float* __restrict__ We)
{
    int idx = blockIdx.x * 256 + threadIdx.x;
    if (idx < 39*64) {
        int f = idx >> 6, u = idx & 63;
        g_W2[idx] = pack2(We[f*CH + u], We[f*CH + u + 64]);
    }
}

// ======================================================================
// Kernel 4: edge GEMM + bias + LN.
// 128 threads/block, TILE=32 edges. Thread (h=t>>6 in {0,1}, u=t&63):
//   edges [h*16, h*16+16), channel pair (u, u+64).
// E=16 per thread rebalances LDS wavefronts (40/blk/f) vs fma (32 cyc/blk/f).
// ======================================================================
#define TILE 32
__global__ void __launch_bounds__(128)
egemm_kernel(const float* __restrict__ be,
             const float* __restrict__ ge, const float* __restrict__ betae,
             float* __restrict__ out)
{
    const int e0 = blockIdx.x * TILE;
    const int t  = threadIdx.x;
    const int h  = t >> 6;            // 0..1 (edge half)
    const int u  = t & 63;            // channel pair id

    __shared__ __align__(16) unsigned long long W2s[39*64];   // 19,968 B
    __shared__ __align__(16) unsigned long long ftd[39*32];   //  9,984 B
    __shared__ float mu_s[TILE], irs_s[TILE];
    __shared__ float red[2][TILE];

    // copy pre-paired weights (LDG.128 -> STS.128)
    {
        const ulonglong2* src = reinterpret_cast<const ulonglong2*>(g_W2);
        ulonglong2* dst = reinterpret_cast<ulonglong2*>(W2s);
        #pragma unroll
        for (int k = 0; k < 10; k++) {
            int idx = t + k*128;
            if (idx < 39*32) dst[idx] = src[idx];
        }
    }
    // load features for this tile, duplicated: ftd[f*32+e] = (F,F)
    #pragma unroll
    for (int k = 0; k < 10; k++) {
        int idx = t + k*128;
        if (idx < 39*TILE) {
            int f = idx >> 5, e = idx & 31;
            float v = g_feat[(size_t)f * NEDGE + e0 + e];
            ftd[idx] = pack2(v, v);
        }
    }
    __syncthreads();

    unsigned long long acc[16];
    {
        unsigned long long bi = pack2(be[u], be[u + 64]);
        #pragma unroll
        for (int m = 0; m < 16; m++) acc[m] = bi;
    }

    #pragma unroll
    for (int f = 0; f < 39; f++) {
        unsigned long long w = W2s[f*64 + u];                       // LDS.64
        const ulonglong2* fp =
            reinterpret_cast<const ulonglong2*>(&ftd[f*32 + h*16]); // broadcast
        ulonglong2 v0 = fp[0];
        ulonglong2 v1 = fp[1];
        fma2(acc[0], w, v0.x);  fma2(acc[1], w, v0.y);
        fma2(acc[2], w, v1.x);  fma2(acc[3], w, v1.y);
        ulonglong2 v2 = fp[2];
        ulonglong2 v3 = fp[3];
        fma2(acc[4], w, v2.x);  fma2(acc[5], w, v2.y);
        fma2(acc[6], w, v3.x);  fma2(acc[7], w, v3.y);
        ulonglong2 v4 = fp[4];
        ulonglong2 v5 = fp[5];
        fma2(acc[8],  w, v4.x); fma2(acc[9],  w, v4.y);
        fma2(acc[10], w, v5.x); fma2(acc[11], w, v5.y);
        ulonglong2 v6 = fp[6];
        ulonglong2 v7 = fp[7];
        fma2(acc[12], w, v6.x); fma2(acc[13], w, v6.y);
        fma2(acc[14], w, v7.x); fma2(acc[15], w, v7.y);
    }

    // ---- LN stats, two-pass from registers ----
    // warp layout: warp0=(h0,u0-31), warp1=(h0,u32-63), warp2=(h1,u0-31), warp3=(h1,u32-63)
    const int lane = t & 31;
    const int par  = (t >> 5) & 1;     // which 32-channel-pair half

    float s[16];
    #pragma unroll
    for (int m = 0; m < 16; m++) {
        float2 p = unpack2(acc[m]);
        s[m] = p.x + p.y;
    }
    #pragma unroll
    for (int m = 0; m < 16; m++)
        #pragma unroll
        for (int o = 16; o > 0; o >>= 1)
            s[m] += __shfl_xor_sync(0xffffffffu, s[m], o);
    if (lane == 0) {
        #pragma unroll
        for (int m = 0; m < 16; m++) red[par][h*16 + m] = s[m];
    }
    __syncthreads();
    if (t < TILE) mu_s[t] = (red[0][t] + red[1][t]) * (1.f/128.f);
    __syncthreads();

    #pragma unroll
    for (int m = 0; m < 16; m++) {
        float mu = mu_s[h*16 + m];
        float2 p = unpack2(acc[m]);
        float d0 = p.x - mu, d1 = p.y - mu;
        s[m] = d0*d0 + d1*d1;
    }
    #pragma unroll
    for (int m = 0; m < 16; m++)
        #pragma unroll
        for (int o = 16; o > 0; o >>= 1)
            s[m] += __shfl_xor_sync(0xffffffffu, s[m], o);
    if (lane == 0) {
        #pragma unroll
        for (int m = 0; m < 16; m++) red[par][h*16 + m] = s[m];
    }
    __syncthreads();
    if (t < TILE)
        irs_s[t] = 1.f / sqrtf((red[0][t] + red[1][t]) * (1.f/128.f) + 1e-5f);
    __syncthreads();

    const float gg0 = ge[u], gg1 = ge[u + 64];
    const float bb0 = betae[u], bb1 = betae[u + 64];
    const size_t base = E_OFF + (size_t)e0 * CH;
    #pragma unroll
    for (int m = 0; m < 16; m++) {
        int e = h*16 + m;
        float mu = mu_s[e], is = irs_s[e];
        float2 p = unpack2(acc[m]);
        out[base + (size_t)e * CH + u]      = (p.x - mu) * is * gg0 + bb0;
        out[base + (size_t)e * CH + u + 64] = (p.y - mu) * is * gg1 + bb1;
    }
}

// ======================================================================
extern "C" void kernel_launch(void* const* d_in, const int* in_sizes, int n_in,
                              void* d_out, int out_size)
{
    const float* X      = (const float*)d_in[0];
    // d_in[1] = mask (all ones; unused)
    const float* W_node = (const float*)d_in[2];
    const float* b_node = (const float*)d_in[3];
    const float* g_node = (const float*)d_in[4];
    const float* be_node= (const float*)d_in[5];
    const float* W_edge = (const float*)d_in[6];
    const float* b_edge = (const float*)d_in[7];
    const float* g_edge = (const float*)d_in[8];
    const float* be_edge= (const float*)d_in[9];
    float* out = (float*)d_out;

    knn_kernel<<<dim3(LL/16, NB), 512>>>(X, out);
    node_kernel<<<NB*LL, 128>>>(X, W_node, b_node, g_node, be_node, out);
    efeat_kernel<<<(NEDGE + 255)/256, 256>>>(X);
    packw_kernel<<<(39*64 + 255)/256, 256>>>(W_edge);
    egemm_kernel<<<NEDGE/TILE, 128>>>(b_edge, g_edge, be_edge, out);
}

// round 7
// speedup vs baseline: 1.8466x; 1.1777x over previous
#include <cuda_runtime.h>
#include <cstdint>
#include <cstddef>

#define NB 8
#define LL 2048
#define KK 30
#define CH 128
#define NEDGE (NB*LL*KK)   // 491520

static constexpr size_t V_SIZE = (size_t)NB * LL * CH;           // 2,097,152
static constexpr size_t E_SIZE = (size_t)NB * LL * KK * CH;      // 62,914,560
static constexpr size_t E_OFF  = V_SIZE;
static constexpr size_t I_OFF  = V_SIZE + E_SIZE;

// -------- scratch (device globals; no allocations allowed) --------
__device__ float g_dnb[NB*LL*KK];      // sorted neighbor distances
__device__ int   g_eidx[NB*LL*KK];     // sorted neighbor indices
__device__ float g_O[NB*LL*9];         // per-residue orientation frames
__device__ float g_feat[39*NEDGE];     // edge features, f-major
__device__ ulonglong2 g_W4[39*32];     // quad weights: ((w_u,w_u+32),(w_u+64,w_u+96))

// ---------------- small helpers ----------------
__device__ __forceinline__ float dot3(const float* a, const float* b) {
    return a[0]*b[0] + a[1]*b[1] + a[2]*b[2];
}
__device__ __forceinline__ void cross3(const float* a, const float* b, float* o) {
    o[0] = a[1]*b[2] - a[2]*b[1];
    o[1] = a[2]*b[0] - a[0]*b[2];
    o[2] = a[0]*b[1] - a[1]*b[0];
}
__device__ __forceinline__ void norm3(float* v) {
    float n = sqrtf(v[0]*v[0] + v[1]*v[1] + v[2]*v[2]);
    n = fmaxf(n, 1e-12f);
    v[0] /= n; v[1] /= n; v[2] /= n;
}
__device__ __forceinline__ float sgnf(float v) {
    return (v > 0.f) ? 1.f : ((v < 0.f) ? -1.f : 0.f);
}

// packed fp32x2 ops (sm_103a)
__device__ __forceinline__ unsigned long long pack2(float x, float y) {
    unsigned long long r;
    asm("mov.b64 %0, {%1, %2};" : "=l"(r) : "f"(x), "f"(y));
    return r;
}
__device__ __forceinline__ float2 unpack2(unsigned long long v) {
    float2 r;
    asm("mov.b64 {%0, %1}, %2;" : "=f"(r.x), "=f"(r.y) : "l"(v));
    return r;
}
__device__ __forceinline__ void fma2(unsigned long long& d,
                                     unsigned long long a, unsigned long long b) {
    asm("fma.rn.f32x2 %0, %1, %2, %0;" : "+l"(d) : "l"(a), "l"(b));
}

// ======================================================================
// Kernel 1: exact KNN matching jax.lax.top_k(-D) bit-for-bit.
// ======================================================================
__global__ void __launch_bounds__(512)
knn_kernel(const float* __restrict__ X, float* __restrict__ out)
{
    __shared__ float4 pts[LL];                 // 32 KB
    const int b = blockIdx.y;
    const float* Xb = X + (size_t)b * LL * 12;

    for (int t = threadIdx.x; t < LL; t += blockDim.x) {
        pts[t] = make_float4(Xb[t*12 + 3], Xb[t*12 + 4], Xb[t*12 + 5], 0.f);
    }
    __syncthreads();

    const int wid  = threadIdx.x >> 5;
    const int lane = threadIdx.x & 31;
    const int i = blockIdx.x * 16 + wid;       // query index
    const float4 q = pts[i];
    const unsigned FULL = 0xffffffffu;

    auto exact_key = [&](float px, float py, float pz, int j) -> unsigned long long {
        float dx = __fsub_rn(px, q.x);
        float dy = __fsub_rn(py, q.y);
        float dz = __fsub_rn(pz, q.z);
        float d2 = __fadd_rn(__fadd_rn(__fmul_rn(dx,dx), __fmul_rn(dy,dy)),
                             __fmul_rn(dz,dz));
        float D  = sqrtf(__fadd_rn(d2, 1e-6f));   // sqrt.rn — matches XLA
        return ((unsigned long long)__float_as_uint(D) << 32) | (unsigned)j;
    };

    float4 p = pts[lane];
    unsigned long long cur = exact_key(p.x, p.y, p.z, lane);

    unsigned long long thr;
    float thr_d2;
    auto update_thr = [&]() {
        unsigned hi = __reduce_max_sync(FULL, (unsigned)(cur >> 32));
        unsigned lo = __reduce_max_sync(FULL,
                          ((unsigned)(cur >> 32) == hi) ? (unsigned)cur : 0u);
        thr = ((unsigned long long)hi << 32) | lo;
        float D = __uint_as_float(hi);
        thr_d2 = D * D * 1.00002f;     // conservative vs fma/rn/sqrt ulps
    };
    update_thr();

    for (int t = 1; t < LL/32; t++) {
        const int j = t*32 + lane;
        p = pts[j];
        float dx = p.x - q.x, dy = p.y - q.y, dz = p.z - q.z;
        float d2c = fmaf(dx, dx, fmaf(dy, dy, dz*dz));
        bool pass = d2c <= thr_d2;
        unsigned bal = __ballot_sync(FULL, pass);
        if (!bal) continue;                       // warp-uniform
        unsigned long long kk = pass ? exact_key(p.x, p.y, p.z, j) : ~0ull;
        do {
            int s = __ffs(bal) - 1;
            bal &= bal - 1;
            unsigned long long bk = __shfl_sync(FULL, kk, s);
            if (bk < thr) {                       // warp-uniform
                unsigned m = __ballot_sync(FULL, cur == thr);  // keys unique
                if (lane == (__ffs(m) - 1)) cur = bk;
                update_thr();
            }
        } while (bal);
    }

    // bitonic sort 32 keys across the warp, ascending
    #pragma unroll
    for (int k = 2; k <= 32; k <<= 1) {
        #pragma unroll
        for (int j = k >> 1; j >= 1; j >>= 1) {
            unsigned long long ok = __shfl_xor_sync(FULL, cur, j);
            bool up    = ((lane & k) == 0);
            bool lower = ((lane & j) == 0);
            bool mineLess = (cur < ok);
            bool takeOther = up ? (lower ? !mineLess : mineLess)
                                : (lower ? mineLess : !mineLess);
            if (takeOther) cur = ok;
        }
    }

    if (lane < KK) {
        int e = (b*LL + i)*KK + lane;
        int nidx = (int)(cur & 0xffffffffu);
        g_dnb[e]  = __uint_as_float((unsigned)(cur >> 32));
        g_eidx[e] = nidx;
        out[I_OFF + (size_t)e] = (float)nidx;
    }
}

// ======================================================================
// Kernel 2: node features (dihedrals -> 6) @ W_node + LN; also builds O.
// ======================================================================
__global__ void __launch_bounds__(128)
node_kernel(const float* __restrict__ X,
            const float* __restrict__ Wn, const float* __restrict__ bn,
            const float* __restrict__ gn, const float* __restrict__ betan,
            float* __restrict__ out)
{
    const int idx = blockIdx.x;          // b*LL + i
    const int b = idx / LL, i = idx % LL;
    const float* Xb = X + (size_t)b * LL * 12;

    __shared__ float feat[6];
    __shared__ float red[4];
    __shared__ float stats[2];

    const int tid = threadIdx.x;
    const int wid = tid >> 5, lane = tid & 31;

    if (tid < 3) {
        int t = 3*i + tid - 1;
        float ang = 0.f;
        if (t >= 0 && t <= 3*LL - 4) {
            float P[4][3];
            #pragma unroll
            for (int a = 0; a < 4; a++) {
                int g = t + a;
                const float* ptr = Xb + (g/3)*12 + (g%3)*3;
                P[a][0] = ptr[0]; P[a][1] = ptr[1]; P[a][2] = ptr[2];
            }
            float u2[3], u1[3], u0[3], n2[3], n1[3];
            #pragma unroll
            for (int c = 0; c < 3; c++) {
                u2[c] = P[1][c] - P[0][c];
                u1[c] = P[2][c] - P[1][c];
                u0[c] = P[3][c] - P[2][c];
            }
            norm3(u2); norm3(u1); norm3(u0);
            cross3(u2, u1, n2); norm3(n2);
            cross3(u1, u0, n1); norm3(n1);
            float cd = dot3(n2, n1);
            cd = fminf(fmaxf(cd, -1.f + 1e-7f), 1.f - 1e-7f);
            ang = sgnf(dot3(u2, n1)) * acosf(cd);
        }
        feat[tid]     = cosf(ang);
        feat[tid + 3] = sinf(ang);
    }
    if (tid == 3) {
        const float* pr = Xb + i*12;
        float N[3]  = {pr[0], pr[1], pr[2]};
        float CA[3] = {pr[3], pr[4], pr[5]};
        float C[3]  = {pr[6], pr[7], pr[8]};
        float nca[3], cac[3];
        #pragma unroll
        for (int c = 0; c < 3; c++) { nca[c] = CA[c] - N[c]; cac[c] = C[c] - CA[c]; }
        norm3(nca); norm3(cac);
        float n1[3]; cross3(nca, cac, n1); norm3(n1);
        float bb[3];
        #pragma unroll
        for (int c = 0; c < 3; c++) bb[c] = cac[c] - nca[c];
        norm3(bb);
        float xx[3]; cross3(bb, n1, xx); norm3(xx);
        float* o = g_O + (size_t)idx * 9;
        o[0]=bb[0]; o[1]=bb[1]; o[2]=bb[2];
        o[3]=n1[0]; o[4]=n1[1]; o[5]=n1[2];
        o[6]=xx[0]; o[7]=xx[1]; o[8]=xx[2];
    }
    __syncthreads();

    float acc = bn[tid];
    #pragma unroll
    for (int f = 0; f < 6; f++) acc += feat[f] * Wn[f*CH + tid];

    float s = acc;
    #pragma unroll
    for (int o = 16; o > 0; o >>= 1) s += __shfl_down_sync(0xffffffffu, s, o);
    if (lane == 0) red[wid] = s;
    __syncthreads();
    if (tid == 0) stats[0] = (red[0] + red[1] + red[2] + red[3]) * (1.f/128.f);
    __syncthreads();
    float d = acc - stats[0];
    float s2 = d * d;
    #pragma unroll
    for (int o = 16; o > 0; o >>= 1) s2 += __shfl_down_sync(0xffffffffu, s2, o);
    if (lane == 0) red[wid] = s2;
    __syncthreads();
    if (tid == 0) {
        float var = (red[0] + red[1] + red[2] + red[3]) * (1.f/128.f);
        stats[1] = sqrtf(var + 1e-5f);
    }
    __syncthreads();
    out[(size_t)idx * CH + tid] = d / stats[1] * gn[tid] + betan[tid];
}

// ======================================================================
// Kernel 3: edge features (39 per edge), one thread per edge, f-major out.
// Block 0 additionally packs the quad weights into g_W4.
// ======================================================================
__global__ void __launch_bounds__(256)
efeat_kernel(const float* __restrict__ X, const float* __restrict__ We)
{
    if (blockIdx.x == 0) {
        for (int idx = threadIdx.x; idx < 39*32; idx += 256) {
            int f = idx >> 5, u = idx & 31;
            g_W4[idx] = make_ulonglong2(
                pack2(We[f*CH + u],      We[f*CH + u + 32]),
                pack2(We[f*CH + u + 64], We[f*CH + u + 96]));
        }
    }

    const int e = blockIdx.x * 256 + threadIdx.x;
    if (e >= NEDGE) return;
    const int bi = e / KK;                 // b*LL + i
    const int b = bi / LL, i = bi % LL;
    const int j = g_eidx[e];
    const float D = g_dnb[e];

    float F[39];

    const float d = (float)(j - i);
    const float cfac = -0.5756462732485115f;   // -(log(10000)/16)
    #pragma unroll
    for (int m = 0; m < 8; m++) {
        float freq = expf((float)(2*m) * cfac);
        float a = d * freq;
        F[m]     = cosf(a);
        F[8 + m] = sinf(a);
    }

    #pragma unroll
    for (int m = 0; m < 16; m++) {
        float mu = (float)m * (20.0f / 15.0f);
        float t = (D - mu) / 1.25f;
        F[16 + m] = expf(-(t * t));
    }

    const float* Oi = g_O + (size_t)bi * 9;
    const float* Oj = g_O + ((size_t)b*LL + j) * 9;
    float oi[9], oj[9];
    #pragma unroll
    for (int t = 0; t < 9; t++) { oi[t] = Oi[t]; oj[t] = Oj[t]; }
    const float* Xi = X + (size_t)bi * 12 + 3;
    const float* Xj = X + ((size_t)b*LL + j) * 12 + 3;
    float dX[3] = {Xj[0]-Xi[0], Xj[1]-Xi[1], Xj[2]-Xi[2]};
    float du[3] = { oi[0]*dX[0] + oi[1]*dX[1] + oi[2]*dX[2],
                    oi[3]*dX[0] + oi[4]*dX[1] + oi[5]*dX[2],
                    oi[6]*dX[0] + oi[7]*dX[1] + oi[8]*dX[2] };
    norm3(du);
    F[32] = du[0]; F[33] = du[1]; F[34] = du[2];

    float R[3][3];
    #pragma unroll
    for (int r = 0; r < 3; r++)
        #pragma unroll
        for (int c = 0; c < 3; c++)
            R[r][c] = oi[r]*oj[c] + oi[3+r]*oj[3+c] + oi[6+r]*oj[6+c];

    float Rxx = R[0][0], Ryy = R[1][1], Rzz = R[2][2];
    float m0 = 0.5f * sqrtf(fabsf((1.f + ( Rxx - Ryy - Rzz)) + 1e-10f));
    float m1 = 0.5f * sqrtf(fabsf((1.f + (-Rxx + Ryy - Rzz)) + 1e-10f));
    float m2 = 0.5f * sqrtf(fabsf((1.f + (-Rxx - Ryy + Rzz)) + 1e-10f));
    float qx = sgnf(R[2][1] - R[1][2]) * m0;
    float qy = sgnf(R[0][2] - R[2][0]) * m1;
    float qz = sgnf(R[1][0] - R[0][1]) * m2;
    float qw = sqrtf(fmaxf(1.f + Rxx + Ryy + Rzz, 0.f)) * 0.5f;
    float qn = sqrtf(qx*qx + qy*qy + qz*qz + qw*qw);
    qn = fmaxf(qn, 1e-12f);
    F[35] = qx/qn; F[36] = qy/qn; F[37] = qz/qn; F[38] = qw/qn;

    #pragma unroll
    for (int f = 0; f < 39; f++) g_feat[(size_t)f * NEDGE + e] = F[f];
}

// ======================================================================
// Kernel 4: edge GEMM + bias + LN.
// 256 threads/block, TILE=64 edges. Thread (h=t>>5 in 0..7, u=t&31):
//   edges [h*8, h*8+8), channels u, u+32, u+64, u+96.
// One warp owns each edge's full 128 channels -> LN is a pure intra-warp
// butterfly (no smem, no syncs). Mainloop: 1 lane-unique LDS.128 (weight
// quad) + 4 broadcast LDS.128 (features) + 16 FFMA2 per f.
// ======================================================================
#define TILE 64
__global__ void __launch_bounds__(256)
egemm_kernel(const float* __restrict__ be,
             const float* __restrict__ ge, const float* __restrict__ betae,
             float* __restrict__ out)
{
    const int e0 = blockIdx.x * TILE;
    const int t  = threadIdx.x;
    const int h  = t >> 5;            // 0..7: edges [h*8, h*8+8)
    const int u  = t & 31;            // channels u, u+32, u+64, u+96

    __shared__ __align__(16) ulonglong2 W4s[39*32];           // 19,968 B
    __shared__ __align__(16) unsigned long long ftd[39*64];   // 19,968 B

    // prologue: weights (quad-paired) + features (duplicated)
    {
        const ulonglong2* src = reinterpret_cast<const ulonglong2*>(g_W4);
        #pragma unroll
        for (int k = 0; k < 5; k++) {
            int idx = t + k*256;
            if (idx < 39*32) W4s[idx] = src[idx];
        }
    }
    #pragma unroll
    for (int k = 0; k < 10; k++) {
        int idx = t + k*256;
        if (idx < 39*TILE) {
            int f = idx >> 6, e = idx & 63;
            float v = g_feat[(size_t)f * NEDGE + e0 + e];
            ftd[idx] = pack2(v, v);
        }
    }
    __syncthreads();

    // accA[m]: channels (u, u+32); accB[m]: channels (u+64, u+96); edge h*8+m
    unsigned long long accA[8], accB[8];
    {
        unsigned long long bA = pack2(be[u], be[u + 32]);
        unsigned long long bB = pack2(be[u + 64], be[u + 96]);
        #pragma unroll
        for (int m = 0; m < 8; m++) { accA[m] = bA; accB[m] = bB; }
    }

    #pragma unroll
    for (int f = 0; f < 39; f++) {
        ulonglong2 w = W4s[f*32 + u];                               // LDS.128
        const ulonglong2* fp =
            reinterpret_cast<const ulonglong2*>(&ftd[f*64 + h*8]);  // broadcast
        ulonglong2 v0 = fp[0];
        ulonglong2 v1 = fp[1];
        fma2(accA[0], w.x, v0.x);  fma2(accB[0], w.y, v0.x);
        fma2(accA[1], w.x, v0.y);  fma2(accB[1], w.y, v0.y);
        fma2(accA[2], w.x, v1.x);  fma2(accB[2], w.y, v1.x);
        fma2(accA[3], w.x, v1.y);  fma2(accB[3], w.y, v1.y);
        ulonglong2 v2 = fp[2];
        ulonglong2 v3 = fp[3];
        fma2(accA[4], w.x, v2.x);  fma2(accB[4], w.y, v2.x);
        fma2(accA[5], w.x, v2.y);  fma2(accB[5], w.y, v2.y);
        fma2(accA[6], w.x, v3.x);  fma2(accB[6], w.y, v3.x);
        fma2(accA[7], w.x, v3.y);  fma2(accB[7], w.y, v3.y);
    }

    // epilogue: per-edge LN entirely within the warp
    const float g0 = ge[u],        g1 = ge[u + 32];
    const float g2 = ge[u + 64],   g3 = ge[u + 96];
    const float t0 = betae[u],     t1 = betae[u + 32];
    const float t2 = betae[u + 64],t3 = betae[u + 96];

    #pragma unroll
    for (int m = 0; m < 8; m++) {
        float2 a = unpack2(accA[m]);
        float2 bb = unpack2(accB[m]);
        float s1 = (a.x + a.y) + (bb.x + bb.y);
        float s2 = a.x*a.x + a.y*a.y + bb.x*bb.x + bb.y*bb.y;
        #pragma unroll
        for (int o = 16; o > 0; o >>= 1) {
            s1 += __shfl_xor_sync(0xffffffffu, s1, o);
            s2 += __shfl_xor_sync(0xffffffffu, s2, o);
        }
        float mu  = s1 * (1.f/128.f);
        float var = s2 * (1.f/128.f) - mu*mu;
        float ir  = 1.f / sqrtf(var + 1e-5f);

        const size_t base = E_OFF + (size_t)(e0 + h*8 + m) * CH;
        out[base + u]      = (a.x  - mu) * ir * g0 + t0;
        out[base + u + 32] = (a.y  - mu) * ir * g1 + t1;
        out[base + u + 64] = (bb.x - mu) * ir * g2 + t2;
        out[base + u + 96] = (bb.y - mu) * ir * g3 + t3;
    }
}

// ======================================================================
extern "C" void kernel_launch(void* const* d_in, const int* in_sizes, int n_in,
                              void* d_out, int out_size)
{
    const float* X      = (const float*)d_in[0];
    // d_in[1] = mask (all ones; unused)
    const float* W_node = (const float*)d_in[2];
    const float* b_node = (const float*)d_in[3];
    const float* g_node = (const float*)d_in[4];
    const float* be_node= (const float*)d_in[5];
    const float* W_edge = (const float*)d_in[6];
    const float* b_edge = (const float*)d_in[7];
    const float* g_edge = (const float*)d_in[8];
    const float* be_edge= (const float*)d_in[9];
    float* out = (float*)d_out;

    knn_kernel<<<dim3(LL/16, NB), 512>>>(X, out);
    node_kernel<<<NB*LL, 128>>>(X, W_node, b_node, g_node, be_node, out);
    efeat_kernel<<<(NEDGE + 255)/256, 256>>>(X, W_edge);
    egemm_kernel<<<NEDGE/TILE, 256>>>(b_edge, g_edge, be_edge, out);
}

// round 8
// speedup vs baseline: 1.9359x; 1.0483x over previous
#include <cuda_runtime.h>
#include <cstdint>
#include <cstddef>

#define NB 8
#define LL 2048
#define KK 30
#define CH 128
#define NEDGE (NB*LL*KK)   // 491520

static constexpr size_t V_SIZE = (size_t)NB * LL * CH;           // 2,097,152
static constexpr size_t E_SIZE = (size_t)NB * LL * KK * CH;      // 62,914,560
static constexpr size_t E_OFF  = V_SIZE;
static constexpr size_t I_OFF  = V_SIZE + E_SIZE;

// -------- scratch (device globals; no allocations allowed) --------
__device__ float g_dnb[NB*LL*KK];      // sorted neighbor distances
__device__ int   g_eidx[NB*LL*KK];     // sorted neighbor indices
__device__ float g_O[NB*LL*9];         // per-residue orientation frames
__device__ float g_feat[39*NEDGE];     // edge features, f-major
__device__ ulonglong2 g_W4[39*32];     // quad weights: ch 4l..4l+3 as 2 f32x2

// ---------------- small helpers ----------------
__device__ __forceinline__ float dot3(const float* a, const float* b) {
    return a[0]*b[0] + a[1]*b[1] + a[2]*b[2];
}
__device__ __forceinline__ void cross3(const float* a, const float* b, float* o) {
    o[0] = a[1]*b[2] - a[2]*b[1];
    o[1] = a[2]*b[0] - a[0]*b[2];
    o[2] = a[0]*b[1] - a[1]*b[0];
}
__device__ __forceinline__ void norm3(float* v) {
    float n = sqrtf(v[0]*v[0] + v[1]*v[1] + v[2]*v[2]);
    n = fmaxf(n, 1e-12f);
    v[0] /= n; v[1] /= n; v[2] /= n;
}
__device__ __forceinline__ float sgnf(float v) {
    return (v > 0.f) ? 1.f : ((v < 0.f) ? -1.f : 0.f);
}

// packed fp32x2 ops (sm_103a)
__device__ __forceinline__ unsigned long long pack2(float x, float y) {
    unsigned long long r;
    asm("mov.b64 %0, {%1, %2};" : "=l"(r) : "f"(x), "f"(y));
    return r;
}
__device__ __forceinline__ float2 unpack2(unsigned long long v) {
    float2 r;
    asm("mov.b64 {%0, %1}, %2;" : "=f"(r.x), "=f"(r.y) : "l"(v));
    return r;
}
__device__ __forceinline__ void fma2(unsigned long long& d,
                                     unsigned long long a, unsigned long long b) {
    asm("fma.rn.f32x2 %0, %1, %2, %0;" : "+l"(d) : "l"(a), "l"(b));
}

// ======================================================================
// Kernel 1: exact KNN matching jax.lax.top_k(-D) bit-for-bit.
// ======================================================================
__global__ void __launch_bounds__(512)
knn_kernel(const float* __restrict__ X, float* __restrict__ out)
{
    __shared__ float4 pts[LL];                 // 32 KB
    const int b = blockIdx.y;
    const float* Xb = X + (size_t)b * LL * 12;

    for (int t = threadIdx.x; t < LL; t += blockDim.x) {
        pts[t] = make_float4(Xb[t*12 + 3], Xb[t*12 + 4], Xb[t*12 + 5], 0.f);
    }
    __syncthreads();

    const int wid  = threadIdx.x >> 5;
    const int lane = threadIdx.x & 31;
    const int i = blockIdx.x * 16 + wid;       // query index
    const float4 q = pts[i];
    const unsigned FULL = 0xffffffffu;

    auto exact_key = [&](float px, float py, float pz, int j) -> unsigned long long {
        float dx = __fsub_rn(px, q.x);
        float dy = __fsub_rn(py, q.y);
        float dz = __fsub_rn(pz, q.z);
        float d2 = __fadd_rn(__fadd_rn(__fmul_rn(dx,dx), __fmul_rn(dy,dy)),
                             __fmul_rn(dz,dz));
        float D  = sqrtf(__fadd_rn(d2, 1e-6f));   // sqrt.rn — matches XLA
        return ((unsigned long long)__float_as_uint(D) << 32) | (unsigned)j;
    };

    float4 p = pts[lane];
    unsigned long long cur = exact_key(p.x, p.y, p.z, lane);

    unsigned long long thr;
    float thr_d2;
    auto update_thr = [&]() {
        unsigned hi = __reduce_max_sync(FULL, (unsigned)(cur >> 32));
        unsigned lo = __reduce_max_sync(FULL,
                          ((unsigned)(cur >> 32) == hi) ? (unsigned)cur : 0u);
        thr = ((unsigned long long)hi << 32) | lo;
        float D = __uint_as_float(hi);
        thr_d2 = D * D * 1.00002f;     // conservative vs fma/rn/sqrt ulps
    };
    update_thr();

    for (int t = 1; t < LL/32; t++) {
        const int j = t*32 + lane;
        p = pts[j];
        float dx = p.x - q.x, dy = p.y - q.y, dz = p.z - q.z;
        float d2c = fmaf(dx, dx, fmaf(dy, dy, dz*dz));
        bool pass = d2c <= thr_d2;
        unsigned bal = __ballot_sync(FULL, pass);
        if (!bal) continue;                       // warp-uniform
        unsigned long long kk = pass ? exact_key(p.x, p.y, p.z, j) : ~0ull;
        do {
            int s = __ffs(bal) - 1;
            bal &= bal - 1;
            unsigned long long bk = __shfl_sync(FULL, kk, s);
            if (bk < thr) {                       // warp-uniform
                unsigned m = __ballot_sync(FULL, cur == thr);  // keys unique
                if (lane == (__ffs(m) - 1)) cur = bk;
                update_thr();
            }
        } while (bal);
    }

    // bitonic sort 32 keys across the warp, ascending
    #pragma unroll
    for (int k = 2; k <= 32; k <<= 1) {
        #pragma unroll
        for (int j = k >> 1; j >= 1; j >>= 1) {
            unsigned long long ok = __shfl_xor_sync(FULL, cur, j);
            bool up    = ((lane & k) == 0);
            bool lower = ((lane & j) == 0);
            bool mineLess = (cur < ok);
            bool takeOther = up ? (lower ? !mineLess : mineLess)
                                : (lower ? mineLess : !mineLess);
            if (takeOther) cur = ok;
        }
    }

    if (lane < KK) {
        int e = (b*LL + i)*KK + lane;
        int nidx = (int)(cur & 0xffffffffu);
        g_dnb[e]  = __uint_as_float((unsigned)(cur >> 32));
        g_eidx[e] = nidx;
        out[I_OFF + (size_t)e] = (float)nidx;
    }
}

// ======================================================================
// Kernel 2: node features (dihedrals -> 6) @ W_node + LN; also builds O.
// ======================================================================
__global__ void __launch_bounds__(128)
node_kernel(const float* __restrict__ X,
            const float* __restrict__ Wn, const float* __restrict__ bn,
            const float* __restrict__ gn, const float* __restrict__ betan,
            float* __restrict__ out)
{
    const int idx = blockIdx.x;          // b*LL + i
    const int b = idx / LL, i = idx % LL;
    const float* Xb = X + (size_t)b * LL * 12;

    __shared__ float feat[6];
    __shared__ float red[4];
    __shared__ float stats[2];

    const int tid = threadIdx.x;
    const int wid = tid >> 5, lane = tid & 31;

    if (tid < 3) {
        int t = 3*i + tid - 1;
        float ang = 0.f;
        if (t >= 0 && t <= 3*LL - 4) {
            float P[4][3];
            #pragma unroll
            for (int a = 0; a < 4; a++) {
                int g = t + a;
                const float* ptr = Xb + (g/3)*12 + (g%3)*3;
                P[a][0] = ptr[0]; P[a][1] = ptr[1]; P[a][2] = ptr[2];
            }
            float u2[3], u1[3], u0[3], n2[3], n1[3];
            #pragma unroll
            for (int c = 0; c < 3; c++) {
                u2[c] = P[1][c] - P[0][c];
                u1[c] = P[2][c] - P[1][c];
                u0[c] = P[3][c] - P[2][c];
            }
            norm3(u2); norm3(u1); norm3(u0);
            cross3(u2, u1, n2); norm3(n2);
            cross3(u1, u0, n1); norm3(n1);
            float cd = dot3(n2, n1);
            cd = fminf(fmaxf(cd, -1.f + 1e-7f), 1.f - 1e-7f);
            ang = sgnf(dot3(u2, n1)) * acosf(cd);
        }
        feat[tid]     = cosf(ang);
        feat[tid + 3] = sinf(ang);
    }
    if (tid == 3) {
        const float* pr = Xb + i*12;
        float N[3]  = {pr[0], pr[1], pr[2]};
        float CA[3] = {pr[3], pr[4], pr[5]};
        float C[3]  = {pr[6], pr[7], pr[8]};
        float nca[3], cac[3];
        #pragma unroll
        for (int c = 0; c < 3; c++) { nca[c] = CA[c] - N[c]; cac[c] = C[c] - CA[c]; }
        norm3(nca); norm3(cac);
        float n1[3]; cross3(nca, cac, n1); norm3(n1);
        float bb[3];
        #pragma unroll
        for (int c = 0; c < 3; c++) bb[c] = cac[c] - nca[c];
        norm3(bb);
        float xx[3]; cross3(bb, n1, xx); norm3(xx);
        float* o = g_O + (size_t)idx * 9;
        o[0]=bb[0]; o[1]=bb[1]; o[2]=bb[2];
        o[3]=n1[0]; o[4]=n1[1]; o[5]=n1[2];
        o[6]=xx[0]; o[7]=xx[1]; o[8]=xx[2];
    }
    __syncthreads();

    float acc = bn[tid];
    #pragma unroll
    for (int f = 0; f < 6; f++) acc += feat[f] * Wn[f*CH + tid];

    float s = acc;
    #pragma unroll
    for (int o = 16; o > 0; o >>= 1) s += __shfl_down_sync(0xffffffffu, s, o);
    if (lane == 0) red[wid] = s;
    __syncthreads();
    if (tid == 0) stats[0] = (red[0] + red[1] + red[2] + red[3]) * (1.f/128.f);
    __syncthreads();
    float d = acc - stats[0];
    float s2 = d * d;
    #pragma unroll
    for (int o = 16; o > 0; o >>= 1) s2 += __shfl_down_sync(0xffffffffu, s2, o);
    if (lane == 0) red[wid] = s2;
    __syncthreads();
    if (tid == 0) {
        float var = (red[0] + red[1] + red[2] + red[3]) * (1.f/128.f);
        stats[1] = sqrtf(var + 1e-5f);
    }
    __syncthreads();
    out[(size_t)idx * CH + tid] = d / stats[1] * gn[tid] + betan[tid];
}

// ======================================================================
// Kernel 3: edge features (39 per edge), one thread per edge, f-major out.
// Block 0 additionally packs the quad weights (contiguous channels) into g_W4.
// ======================================================================
__global__ void __launch_bounds__(256)
efeat_kernel(const float* __restrict__ X, const float* __restrict__ We)
{
    if (blockIdx.x == 0) {
        for (int idx = threadIdx.x; idx < 39*32; idx += 256) {
            int f = idx >> 5, l = idx & 31;
            g_W4[idx] = make_ulonglong2(
                pack2(We[f*CH + 4*l],     We[f*CH + 4*l + 1]),
                pack2(We[f*CH + 4*l + 2], We[f*CH + 4*l + 3]));
        }
    }

    const int e = blockIdx.x * 256 + threadIdx.x;
    if (e >= NEDGE) return;
    const int bi = e / KK;                 // b*LL + i
    const int b = bi / LL, i = bi % LL;
    const int j = g_eidx[e];
    const float D = g_dnb[e];

    float F[39];

    const float d = (float)(j - i);
    const float cfac = -0.5756462732485115f;   // -(log(10000)/16)
    #pragma unroll
    for (int m = 0; m < 8; m++) {
        float freq = expf((float)(2*m) * cfac);
        float a = d * freq;
        F[m]     = cosf(a);
        F[8 + m] = sinf(a);
    }

    #pragma unroll
    for (int m = 0; m < 16; m++) {
        float mu = (float)m * (20.0f / 15.0f);
        float t = (D - mu) / 1.25f;
        F[16 + m] = expf(-(t * t));
    }

    const float* Oi = g_O + (size_t)bi * 9;
    const float* Oj = g_O + ((size_t)b*LL + j) * 9;
    float oi[9], oj[9];
    #pragma unroll
    for (int t = 0; t < 9; t++) { oi[t] = Oi[t]; oj[t] = Oj[t]; }
    const float* Xi = X + (size_t)bi * 12 + 3;
    const float* Xj = X + ((size_t)b*LL + j) * 12 + 3;
    float dX[3] = {Xj[0]-Xi[0], Xj[1]-Xi[1], Xj[2]-Xi[2]};
    float du[3] = { oi[0]*dX[0] + oi[1]*dX[1] + oi[2]*dX[2],
                    oi[3]*dX[0] + oi[4]*dX[1] + oi[5]*dX[2],
                    oi[6]*dX[0] + oi[7]*dX[1] + oi[8]*dX[2] };
    norm3(du);
    F[32] = du[0]; F[33] = du[1]; F[34] = du[2];

    float R[3][3];
    #pragma unroll
    for (int r = 0; r < 3; r++)
        #pragma unroll
        for (int c = 0; c < 3; c++)
            R[r][c] = oi[r]*oj[c] + oi[3+r]*oj[3+c] + oi[6+r]*oj[6+c];

    float Rxx = R[0][0], Ryy = R[1][1], Rzz = R[2][2];
    float m0 = 0.5f * sqrtf(fabsf((1.f + ( Rxx - Ryy - Rzz)) + 1e-10f));
    float m1 = 0.5f * sqrtf(fabsf((1.f + (-Rxx + Ryy - Rzz)) + 1e-10f));
    float m2 = 0.5f * sqrtf(fabsf((1.f + (-Rxx - Ryy + Rzz)) + 1e-10f));
    float qx = sgnf(R[2][1] - R[1][2]) * m0;
    float qy = sgnf(R[0][2] - R[2][0]) * m1;
    float qz = sgnf(R[1][0] - R[0][1]) * m2;
    float qw = sqrtf(fmaxf(1.f + Rxx + Ryy + Rzz, 0.f)) * 0.5f;
    float qn = sqrtf(qx*qx + qy*qy + qz*qz + qw*qw);
    qn = fmaxf(qn, 1e-12f);
    F[35] = qx/qn; F[36] = qy/qn; F[37] = qz/qn; F[38] = qw/qn;

    #pragma unroll
    for (int f = 0; f < 39; f++) g_feat[(size_t)f * NEDGE + e] = F[f];
}

// ======================================================================
// Kernel 4: edge GEMM + bias + LN.
// 256 threads/block, TILE=128 edges. Warp h (0..7) owns edges
// [h*16, h*16+16); lane l owns channels 4l..4l+3.
// Per f: 1 lane-unique LDS.128 (weight quad) + 8 broadcast LDS.128
// (16 duplicated features) + 32 FFMA2. Epilogue: in-warp LN butterfly,
// one coalesced STG.128 per edge per lane.
// ======================================================================
#define TILE 128
__global__ void __launch_bounds__(256, 2)
egemm_kernel(const float* __restrict__ be,
             const float* __restrict__ ge, const float* __restrict__ betae,
             float* __restrict__ out)
{
    const int e0 = blockIdx.x * TILE;
    const int t  = threadIdx.x;
    const int h  = t >> 5;            // warp id: edges [h*16, h*16+16)
    const int l  = t & 31;            // lane: channels 4l..4l+3

    __shared__ __align__(16) ulonglong2 W4s[39*32];           // 19,968 B
    __shared__ __align__(16) unsigned long long ftd[39*TILE]; // 39,936 B

    // prologue: weights (quad-paired) + features (duplicated)
    {
        const ulonglong2* src = reinterpret_cast<const ulonglong2*>(g_W4);
        #pragma unroll
        for (int k = 0; k < 5; k++) {
            int idx = t + k*256;
            if (idx < 39*32) W4s[idx] = src[idx];
        }
    }
    #pragma unroll
    for (int k = 0; k < 20; k++) {
        int idx = t + k*256;
        if (idx < 39*TILE) {
            int f = idx >> 7, e = idx & 127;
            float v = g_feat[(size_t)f * NEDGE + e0 + e];
            ftd[idx] = pack2(v, v);
        }
    }
    __syncthreads();

    // accA[m]: channels (4l, 4l+1); accB[m]: channels (4l+2, 4l+3); edge h*16+m
    unsigned long long accA[16], accB[16];
    {
        float4 b4 = reinterpret_cast<const float4*>(be)[l];
        unsigned long long bA = pack2(b4.x, b4.y);
        unsigned long long bB = pack2(b4.z, b4.w);
        #pragma unroll
        for (int m = 0; m < 16; m++) { accA[m] = bA; accB[m] = bB; }
    }

    #pragma unroll
    for (int f = 0; f < 39; f++) {
        ulonglong2 w = W4s[f*32 + l];                               // LDS.128
        const ulonglong2* fp =
            reinterpret_cast<const ulonglong2*>(&ftd[f*TILE + h*16]); // broadcast
        #pragma unroll
        for (int k = 0; k < 8; k++) {
            ulonglong2 v = fp[k];
            fma2(accA[2*k  ], w.x, v.x);  fma2(accB[2*k  ], w.y, v.x);
            fma2(accA[2*k+1], w.x, v.y);  fma2(accB[2*k+1], w.y, v.y);
        }
    }

    // epilogue: per-edge LN entirely within the warp, STG.128 stores
    float4 g4 = reinterpret_cast<const float4*>(ge)[l];
    float4 t4 = reinterpret_cast<const float4*>(betae)[l];

    #pragma unroll
    for (int m = 0; m < 16; m++) {
        float2 a = unpack2(accA[m]);
        float2 bb = unpack2(accB[m]);
        float s1 = (a.x + a.y) + (bb.x + bb.y);
        float s2 = a.x*a.x + a.y*a.y + bb.x*bb.x + bb.y*bb.y;
        #pragma unroll
        for (int o = 16; o > 0; o >>= 1) {
            s1 += __shfl_xor_sync(0xffffffffu, s1, o);
            s2 += __shfl_xor_sync(0xffffffffu, s2, o);
        }
        float mu  = s1 * (1.f/128.f);
        float var = s2 * (1.f/128.f) - mu*mu;
        float ir  = 1.f / sqrtf(var + 1e-5f);

        float4 o4;
        o4.x = (a.x  - mu) * ir * g4.x + t4.x;
        o4.y = (a.y  - mu) * ir * g4.y + t4.y;
        o4.z = (bb.x - mu) * ir * g4.z + t4.z;
        o4.w = (bb.y - mu) * ir * g4.w + t4.w;
        const size_t base = E_OFF + (size_t)(e0 + h*16 + m) * CH;
        reinterpret_cast<float4*>(out + base)[l] = o4;
    }
}

// ======================================================================
extern "C" void kernel_launch(void* const* d_in, const int* in_sizes, int n_in,
                              void* d_out, int out_size)
{
    const float* X      = (const float*)d_in[0];
    // d_in[1] = mask (all ones; unused)
    const float* W_node = (const float*)d_in[2];
    const float* b_node = (const float*)d_in[3];
    const float* g_node = (const float*)d_in[4];
    const float* be_node= (const float*)d_in[5];
    const float* W_edge = (const float*)d_in[6];
    const float* b_edge = (const float*)d_in[7];
    const float* g_edge = (const float*)d_in[8];
    const float* be_edge= (const float*)d_in[9];
    float* out = (float*)d_out;

    knn_kernel<<<dim3(LL/16, NB), 512>>>(X, out);
    node_kernel<<<NB*LL, 128>>>(X, W_node, b_node, g_node, be_node, out);
    efeat_kernel<<<(NEDGE + 255)/256, 256>>>(X, W_edge);
    egemm_kernel<<<NEDGE/TILE, 256>>>(b_edge, g_edge, be_edge, out);
}